// round 12
// baseline (speedup 1.0000x reference)
#include <cuda_runtime.h>
#include <cuda_bf16.h>
#include <math.h>
#include <stdint.h>

#define B_ 2
#define N_ 2048
#define D_ 1024
#define H_ 16
#define DH_ 64
#define SCALE_ 0.125f   /* 64^-0.5, exact power of two */

/* ------------------------------------------------------------------ */
/* device scratch                                                      */
/* ------------------------------------------------------------------ */
__device__ float g_xr [4096 * 1024];   /* tf32-rounded x      */
__device__ float g_wqr[3072 * 1024];   /* tf32-rounded W_qkv  */
__device__ float g_wor[1024 * 1024];   /* tf32-rounded W_out  */
__device__ __nv_bfloat16 g_qh[B_*H_*N_*DH_], g_ql[B_*H_*N_*DH_];
__device__ __nv_bfloat16 g_kh[B_*H_*N_*DH_], g_kl[B_*H_*N_*DH_];
__device__ __nv_bfloat16 g_vh[B_*H_*N_*DH_], g_vl[B_*H_*N_*DH_];
__device__ float         g_aor[B_*N_*D_];  /* tf32-rounded ao */

/* ------------------------------------------------------------------ */
/* helpers                                                             */
/* ------------------------------------------------------------------ */
__device__ __forceinline__ uint32_t smem_u32(const void* p) {
    uint32_t a;
    asm("{ .reg .u64 t; cvta.to.shared.u64 t, %1; cvt.u32.u64 %0, t; }"
        : "=r"(a) : "l"(p));
    return a;
}

/* swizzle for 128B-row fp32 tiles: chunk' = chunk ^ (row & 7) */
__device__ __forceinline__ uint32_t swzA(uint32_t o) {
    return o ^ (((o >> 7) & 7u) << 4);
}

__device__ __forceinline__ void ldsm4(uint32_t addr, uint32_t& r0, uint32_t& r1,
                                      uint32_t& r2, uint32_t& r3) {
    asm volatile("ldmatrix.sync.aligned.m8n8.x4.shared.b16 {%0,%1,%2,%3}, [%4];"
                 : "=r"(r0), "=r"(r1), "=r"(r2), "=r"(r3) : "r"(addr));
}

__device__ __forceinline__ void ldsm4t(uint32_t addr, uint32_t& r0, uint32_t& r1,
                                       uint32_t& r2, uint32_t& r3) {
    asm volatile("ldmatrix.sync.aligned.m8n8.x4.trans.shared.b16 {%0,%1,%2,%3}, [%4];"
                 : "=r"(r0), "=r"(r1), "=r"(r2), "=r"(r3) : "r"(addr));
}

__device__ __forceinline__ void mma16816(float* c,
                                         uint32_t a0, uint32_t a1, uint32_t a2, uint32_t a3,
                                         uint32_t b0, uint32_t b1) {
    asm volatile(
        "mma.sync.aligned.m16n8k16.row.col.f32.bf16.bf16.f32 "
        "{%0,%1,%2,%3}, {%4,%5,%6,%7}, {%8,%9}, {%0,%1,%2,%3};"
        : "+f"(c[0]), "+f"(c[1]), "+f"(c[2]), "+f"(c[3])
        : "r"(a0), "r"(a1), "r"(a2), "r"(a3), "r"(b0), "r"(b1));
}

__device__ __forceinline__ void mma_tf32(float* c,
                                         uint32_t a0, uint32_t a1, uint32_t a2, uint32_t a3,
                                         uint32_t b0, uint32_t b1) {
    asm volatile(
        "mma.sync.aligned.m16n8k8.row.col.f32.tf32.tf32.f32 "
        "{%0,%1,%2,%3}, {%4,%5,%6,%7}, {%8,%9}, {%0,%1,%2,%3};"
        : "+f"(c[0]), "+f"(c[1]), "+f"(c[2]), "+f"(c[3])
        : "r"(a0), "r"(a1), "r"(a2), "r"(a3), "r"(b0), "r"(b1));
}

__device__ __forceinline__ void split2(float x, float y, uint32_t& hi, uint32_t& lo) {
    __nv_bfloat162 h = __floats2bfloat162_rn(x, y);
    float rx = x - __bfloat162float(h.x);
    float ry = y - __bfloat162float(h.y);
    __nv_bfloat162 l = __floats2bfloat162_rn(rx, ry);
    hi = *reinterpret_cast<uint32_t*>(&h);
    lo = *reinterpret_cast<uint32_t*>(&l);
}

__device__ __forceinline__ void cp16(uint32_t saddr, const void* g) {
    asm volatile("cp.async.cg.shared.global [%0], [%1], 16;"
                 :: "r"(saddr), "l"(g) : "memory");
}
__device__ __forceinline__ void cp_commit() {
    asm volatile("cp.async.commit_group;" ::: "memory");
}
template <int NN>
__device__ __forceinline__ void cp_wait() {
    asm volatile("cp.async.wait_group %0;" :: "n"(NN) : "memory");
}

/* ------------------------------------------------------------------ */
/* round kernel: fp32 -> tf32-rounded fp32 (rna)                       */
/* ------------------------------------------------------------------ */
__global__ void __launch_bounds__(256)
round_tf32(const float* __restrict__ src, float* __restrict__ dst, int n4)
{
    int i      = blockIdx.x * blockDim.x + threadIdx.x;
    int stride = gridDim.x * blockDim.x;
    for (; i < n4; i += stride) {
        float4 v = reinterpret_cast<const float4*>(src)[i];
        float4 r;
        asm("cvt.rna.tf32.f32 %0, %1;" : "=r"(*(uint32_t*)&r.x) : "f"(v.x));
        asm("cvt.rna.tf32.f32 %0, %1;" : "=r"(*(uint32_t*)&r.y) : "f"(v.y));
        asm("cvt.rna.tf32.f32 %0, %1;" : "=r"(*(uint32_t*)&r.z) : "f"(v.z));
        asm("cvt.rna.tf32.f32 %0, %1;" : "=r"(*(uint32_t*)&r.w) : "f"(v.w));
        reinterpret_cast<float4*>(dst)[i] = r;
    }
}

/* ------------------------------------------------------------------ */
/* TF32 HMMA GEMM on pre-rounded fp32: C = A * W^T.                    */
/* CTA tile 256x128, BK=32, 512 thr (16 warps 4x4), warp tile 64x32.   */
/* 1 CTA/SM; 3-stage cp.async; swizzled pad-free smem; no inner cvt.   */
/* MODE 0: epilogue -> q/k/v bf16 hi/lo (q scaled). MODE 1: fp32 C.    */
/* ------------------------------------------------------------------ */
#define GARR_A (256 * 128u)                 /* A stage bytes (32 KB)  */
#define GARR_W (128 * 128u)                 /* W stage bytes (16 KB)  */
#define GSTAGE_B (GARR_A + GARR_W)          /* 48 KB per stage        */
#define GEMM_SMEM (3 * GSTAGE_B)            /* 147456 B dynamic       */

template <int MODE>
__global__ void __launch_bounds__(512, 1)
gemm_tf32(const float* __restrict__ A, const float* __restrict__ W,
          float* __restrict__ C, int K, int Nout)
{
    extern __shared__ float smem[];
    const uint32_t sb = smem_u32(smem);

    const int tid  = threadIdx.x;
    const int lane = tid & 31;
    const int wid  = tid >> 5;        /* 0..15 */
    const int wm   = wid & 3;         /* 64-row slice   */
    const int wn   = wid >> 2;        /* 32-col slice   */

    const int m0 = blockIdx.y * 256;
    const int j0 = blockIdx.x * 128;

    const int q0 = tid & 7;

#define ISSUE_CHUNK(kc, stage)                                                \
    do {                                                                      \
        const int koff = (kc) * 32;                                          \
        const uint32_t st_ = sb + (uint32_t)(stage) * GSTAGE_B;              \
        _Pragma("unroll")                                                     \
        for (int i_ = 0; i_ < 4; i_++) {                                     \
            int r_ = (tid + i_ * 512) >> 3;                                  \
            uint32_t so_ = swzA((uint32_t)(r_ * 128 + q0 * 16));             \
            cp16(st_ + so_, A + (size_t)(m0 + r_) * K + koff + q0 * 4);      \
        }                                                                     \
        _Pragma("unroll")                                                     \
        for (int i_ = 0; i_ < 2; i_++) {                                     \
            int r_ = (tid + i_ * 512) >> 3;                                  \
            uint32_t so_ = swzA((uint32_t)(r_ * 128 + q0 * 16));             \
            cp16(st_ + GARR_A + so_, W + (size_t)(j0 + r_) * K + koff + q0 * 4); \
        }                                                                     \
        cp_commit();                                                         \
    } while (0)

    /* ldsm lane address components */
    const int a_r8 = lane & 7;
    const int a_rh = (lane >> 3) & 1;
    const int a_ch = lane >> 4;
    const int b_rh = lane >> 4;
    const int b_ch = (lane >> 3) & 1;

    float acc[4][4][4];
#pragma unroll
    for (int i = 0; i < 4; i++)
#pragma unroll
        for (int j = 0; j < 4; j++)
#pragma unroll
            for (int c = 0; c < 4; c++) acc[i][j][c] = 0.f;

    const int nchunk = K >> 5;

    ISSUE_CHUNK(0, 0);
    ISSUE_CHUNK(1, 1);

    for (int kc = 0; kc < nchunk; kc++) {
        cp_wait<1>();
        __syncthreads();
        if (kc + 2 < nchunk) {
            int st = kc + 2;
            ISSUE_CHUNK(st, st - (st / 3) * 3);
        }

        const uint32_t stg = sb + (uint32_t)(kc - (kc / 3) * 3) * GSTAGE_B;
        const uint32_t sA  = stg;
        const uint32_t sW  = stg + GARR_A;

#pragma unroll
        for (int ks = 0; ks < 4; ks++) {       /* k8 steps within BK=32 */
            uint32_t a[4][4];
#pragma unroll
            for (int mt = 0; mt < 4; mt++) {
                int row   = wm * 64 + mt * 16 + a_r8 + a_rh * 8;
                int chunk = ks * 2 + a_ch;
                uint32_t addr = sA + swzA((uint32_t)(row * 128 + chunk * 16));
                ldsm4(addr, a[mt][0], a[mt][1], a[mt][2], a[mt][3]);
            }
#pragma unroll
            for (int np = 0; np < 2; np++) {
                int row   = wn * 32 + np * 16 + a_r8 + b_rh * 8;
                int chunk = ks * 2 + b_ch;
                uint32_t addr = sW + swzA((uint32_t)(row * 128 + chunk * 16));
                uint32_t bfr[4];
                ldsm4(addr, bfr[0], bfr[1], bfr[2], bfr[3]);
#pragma unroll
                for (int mt = 0; mt < 4; mt++) {
                    mma_tf32(acc[mt][np * 2 + 0], a[mt][0], a[mt][1], a[mt][2], a[mt][3],
                             bfr[0], bfr[1]);
                    mma_tf32(acc[mt][np * 2 + 1], a[mt][0], a[mt][1], a[mt][2], a[mt][3],
                             bfr[2], bfr[3]);
                }
            }
        }
    }

    /* epilogue */
    const int grp = lane >> 2;
    const int qid = lane & 3;
#pragma unroll
    for (int mt = 0; mt < 4; mt++) {
#pragma unroll
        for (int nt = 0; nt < 4; nt++) {
            const float* c = acc[mt][nt];
            int row = m0 + wm * 64 + mt * 16 + grp;
            int col = j0 + wn * 32 + nt * 8 + qid * 2;
#pragma unroll
            for (int half = 0; half < 2; half++) {
                int m = row + half * 8;
                float vx = c[half * 2], vy = c[half * 2 + 1];
                if (MODE == 0) {
                    int s  = col >> 10;
                    int rr = col & 1023;
                    int h  = rr >> 6;
                    int dh = rr & 63;
                    int b  = m >> 11;
                    int n  = m & 2047;
                    size_t idx = (((size_t)(b * H_ + h) * N_ + n) * DH_ + dh);
                    float sc = (s == 0) ? SCALE_ : 1.f;
                    uint32_t hi, lo;
                    split2(vx * sc, vy * sc, hi, lo);
                    __nv_bfloat16* bhp = (s == 0) ? g_qh : (s == 1) ? g_kh : g_vh;
                    __nv_bfloat16* blp = (s == 0) ? g_ql : (s == 1) ? g_kl : g_vl;
                    *reinterpret_cast<uint32_t*>(bhp + idx) = hi;
                    *reinterpret_cast<uint32_t*>(blp + idx) = lo;
                } else {
                    *reinterpret_cast<float2*>(C + (size_t)m * Nout + col) =
                        make_float2(vx, vy);
                }
            }
        }
    }
}

/* ------------------------------------------------------------------ */
/* Flash-attention (bf16 hi/lo, unchanged from R11). K/V double-       */
/* buffered via cp.async; V fragments via ldmatrix.trans. 2 CTAs/SM.   */
/* Epilogue writes tf32-rounded ao.                                    */
/* ------------------------------------------------------------------ */
#define ASTR 72
#define SM_QH 0
#define SM_QL (128 * ASTR)
#define SM_ST0 (2 * 128 * ASTR)
#define STG_E  (4 * 64 * ASTR)
#define OFF_KH 0
#define OFF_KL (64 * ASTR)
#define OFF_VH (2 * 64 * ASTR)
#define OFF_VL (3 * 64 * ASTR)
#define ATT_SMEM_ELEMS (SM_ST0 + 2 * STG_E)   /* 55296 bf16 = 110592 B */

__global__ void __launch_bounds__(256, 2)
attn_mma()
{
    extern __shared__ __nv_bfloat16 sbuf[];

    const int qt = (N_ / 128 - 1) - (blockIdx.x >> 5);  /* heavy tiles first */
    const int bh = blockIdx.x & 31;
    const int b  = bh >> 4;
    const int h  = bh & 15;

    const int tid  = threadIdx.x;
    const int lane = tid & 31;
    const int w    = tid >> 5;

    const __nv_bfloat16* Qbh = g_qh + (size_t)bh * N_ * DH_;
    const __nv_bfloat16* Qbl = g_ql + (size_t)bh * N_ * DH_;
    const __nv_bfloat16* Kbh = g_kh + (size_t)bh * N_ * DH_;
    const __nv_bfloat16* Kbl = g_kl + (size_t)bh * N_ * DH_;
    const __nv_bfloat16* Vbh = g_vh + (size_t)bh * N_ * DH_;
    const __nv_bfloat16* Vbl = g_vl + (size_t)bh * N_ * DH_;

    const uint32_t sB = smem_u32(sbuf);

    const int kr0 = tid >> 3;
    const int kr1 = (tid + 256) >> 3;
    const int kc8 = (tid & 7) * 8;
    const uint32_t kso0 = (uint32_t)(kr0 * ASTR + kc8) * 2;
    const uint32_t kso1 = (uint32_t)(kr1 * ASTR + kc8) * 2;

#define ISSUE_KV(jt, stage)                                                   \
    do {                                                                      \
        const size_t g0 = (size_t)((jt) * 64 + kr0) * DH_ + kc8;             \
        const size_t g1 = (size_t)((jt) * 64 + kr1) * DH_ + kc8;             \
        const uint32_t st_ = sB + (SM_ST0 + (stage) * STG_E) * 2;            \
        cp16(st_ + OFF_KH * 2 + kso0, Kbh + g0);                             \
        cp16(st_ + OFF_KH * 2 + kso1, Kbh + g1);                             \
        cp16(st_ + OFF_KL * 2 + kso0, Kbl + g0);                             \
        cp16(st_ + OFF_KL * 2 + kso1, Kbl + g1);                             \
        cp16(st_ + OFF_VH * 2 + kso0, Vbh + g0);                             \
        cp16(st_ + OFF_VH * 2 + kso1, Vbh + g1);                             \
        cp16(st_ + OFF_VL * 2 + kso0, Vbl + g0);                             \
        cp16(st_ + OFF_VL * 2 + kso1, Vbl + g1);                             \
        cp_commit();                                                         \
    } while (0)

    ISSUE_KV(0, 0);

    /* ---- load Q tile (pre-scaled, pre-split) ---- */
#pragma unroll
    for (int it = 0; it < 4; it++) {
        int idx = tid + it * 256;
        int r   = idx >> 3;
        int c8  = (idx & 7) * 8;
        size_t g = (size_t)(qt * 128 + r) * DH_ + c8;
        *reinterpret_cast<uint4*>(sbuf + SM_QH + r * ASTR + c8) =
            *reinterpret_cast<const uint4*>(Qbh + g);
        *reinterpret_cast<uint4*>(sbuf + SM_QL + r * ASTR + c8) =
            *reinterpret_cast<const uint4*>(Qbl + g);
    }
    __syncthreads();

    /* ---- Q fragments into registers ---- */
    uint32_t qh[4][4], ql[4][4];
    {
        const uint32_t a0 = sB +
            2u * ((uint32_t)((w * 16 + (lane & 15)) * ASTR) + ((lane >> 4) << 3));
#pragma unroll
        for (int ks = 0; ks < 4; ks++) {
            ldsm4(a0 + SM_QH * 2 + 2u * (ks * 16),
                  qh[ks][0], qh[ks][1], qh[ks][2], qh[ks][3]);
            ldsm4(a0 + SM_QL * 2 + 2u * (ks * 16),
                  ql[ks][0], ql[ks][1], ql[ks][2], ql[ks][3]);
        }
    }

    const uint32_t bpat = 2u * ((uint32_t)(((lane & 7) | ((lane & 16) >> 1)) * ASTR)
                                + (lane & 8));
    const uint32_t vpat = 2u * ((uint32_t)((lane & 15) * ASTR) + ((lane & 16) >> 1));

    float o[8][4];
#pragma unroll
    for (int i = 0; i < 8; i++)
#pragma unroll
        for (int c = 0; c < 4; c++) o[i][c] = 0.f;
    float mrow0 = -INFINITY, mrow1 = -INFINITY;
    float lrow0 = 0.f, lrow1 = 0.f;

    const int qglo   = qt * 128 + w * 16;
    const int ntiles = 2 * qt + 2;

    for (int jt = 0; jt < ntiles; jt++) {
        cp_wait<0>();
        __syncthreads();
        if (jt + 1 < ntiles) ISSUE_KV(jt + 1, (jt + 1) & 1);

        if (jt * 64 > qglo + 15) continue;

        const uint32_t stg = sB + (SM_ST0 + (jt & 1) * STG_E) * 2;
        const uint32_t sKH = stg + OFF_KH * 2;
        const uint32_t sKL = stg + OFF_KL * 2;
        const uint32_t sVH = stg + OFF_VH * 2;
        const uint32_t sVL = stg + OFF_VL * 2;

        /* ---- S = Q K^T ---- */
        float s[8][4];
#pragma unroll
        for (int i = 0; i < 8; i++)
#pragma unroll
            for (int c = 0; c < 4; c++) s[i][c] = 0.f;

#pragma unroll
        for (int ks = 0; ks < 4; ks++) {
#pragma unroll
            for (int np = 0; np < 4; np++) {
                const uint32_t boff = bpat + 2u * (np * 16 * ASTR + ks * 16);
                uint32_t bh4[4], bl4[4];
                ldsm4(sKH + boff, bh4[0], bh4[1], bh4[2], bh4[3]);
                ldsm4(sKL + boff, bl4[0], bl4[1], bl4[2], bl4[3]);
#pragma unroll
                for (int sub = 0; sub < 2; sub++) {
                    float* c = s[np * 2 + sub];
                    mma16816(c, qh[ks][0], qh[ks][1], qh[ks][2], qh[ks][3],
                             bh4[sub * 2], bh4[sub * 2 + 1]);
                    mma16816(c, qh[ks][0], qh[ks][1], qh[ks][2], qh[ks][3],
                             bl4[sub * 2], bl4[sub * 2 + 1]);
                    mma16816(c, ql[ks][0], ql[ks][1], ql[ks][2], ql[ks][3],
                             bh4[sub * 2], bh4[sub * 2 + 1]);
                }
            }
        }

        /* ---- causal mask ---- */
        const int r0 = qglo + (lane >> 2);
        const int r1 = r0 + 8;
        if (jt * 64 + 63 > qglo) {
            const int colb = jt * 64 + (lane & 3) * 2;
#pragma unroll
            for (int nt = 0; nt < 8; nt++) {
                int c0 = colb + nt * 8;
                if (c0 > r0)     s[nt][0] = -INFINITY;
                if (c0 + 1 > r0) s[nt][1] = -INFINITY;
                if (c0 > r1)     s[nt][2] = -INFINITY;
                if (c0 + 1 > r1) s[nt][3] = -INFINITY;
            }
        }

        /* ---- online softmax ---- */
        float mt0 = s[0][0], mt1 = s[0][2];
#pragma unroll
        for (int nt = 0; nt < 8; nt++) {
            mt0 = fmaxf(mt0, fmaxf(s[nt][0], s[nt][1]));
            mt1 = fmaxf(mt1, fmaxf(s[nt][2], s[nt][3]));
        }
        mt0 = fmaxf(mt0, __shfl_xor_sync(0xffffffffu, mt0, 1));
        mt0 = fmaxf(mt0, __shfl_xor_sync(0xffffffffu, mt0, 2));
        mt1 = fmaxf(mt1, __shfl_xor_sync(0xffffffffu, mt1, 1));
        mt1 = fmaxf(mt1, __shfl_xor_sync(0xffffffffu, mt1, 2));

        const float mn0 = fmaxf(mrow0, mt0);
        const float mn1 = fmaxf(mrow1, mt1);
        const float al0 = __expf(mrow0 - mn0);
        const float al1 = __expf(mrow1 - mn1);

        float ps0 = 0.f, ps1 = 0.f;
#pragma unroll
        for (int nt = 0; nt < 8; nt++) {
            s[nt][0] = __expf(s[nt][0] - mn0);
            s[nt][1] = __expf(s[nt][1] - mn0);
            s[nt][2] = __expf(s[nt][2] - mn1);
            s[nt][3] = __expf(s[nt][3] - mn1);
            ps0 += s[nt][0] + s[nt][1];
            ps1 += s[nt][2] + s[nt][3];
        }
        ps0 += __shfl_xor_sync(0xffffffffu, ps0, 1);
        ps0 += __shfl_xor_sync(0xffffffffu, ps0, 2);
        ps1 += __shfl_xor_sync(0xffffffffu, ps1, 1);
        ps1 += __shfl_xor_sync(0xffffffffu, ps1, 2);

        lrow0 = lrow0 * al0 + ps0;
        lrow1 = lrow1 * al1 + ps1;
#pragma unroll
        for (int nt = 0; nt < 8; nt++) {
            o[nt][0] *= al0; o[nt][1] *= al0;
            o[nt][2] *= al1; o[nt][3] *= al1;
        }
        mrow0 = mn0;
        mrow1 = mn1;

        /* ---- O += P V (V fragments via ldmatrix.trans) ---- */
#pragma unroll
        for (int ks = 0; ks < 4; ks++) {
            uint32_t ph[4], pl[4];
            split2(s[2 * ks][0],     s[2 * ks][1],     ph[0], pl[0]);
            split2(s[2 * ks][2],     s[2 * ks][3],     ph[1], pl[1]);
            split2(s[2 * ks + 1][0], s[2 * ks + 1][1], ph[2], pl[2]);
            split2(s[2 * ks + 1][2], s[2 * ks + 1][3], ph[3], pl[3]);
#pragma unroll
            for (int np = 0; np < 4; np++) {
                const uint32_t voff = vpat + 2u * (ks * 16 * ASTR + np * 16);
                uint32_t bh4[4], bl4[4];
                ldsm4t(sVH + voff, bh4[0], bh4[1], bh4[2], bh4[3]);
                ldsm4t(sVL + voff, bl4[0], bl4[1], bl4[2], bl4[3]);
#pragma unroll
                for (int sub = 0; sub < 2; sub++) {
                    float* c = o[np * 2 + sub];
                    mma16816(c, ph[0], ph[1], ph[2], ph[3],
                             bh4[sub * 2], bh4[sub * 2 + 1]);
                    mma16816(c, ph[0], ph[1], ph[2], ph[3],
                             bl4[sub * 2], bl4[sub * 2 + 1]);
                    mma16816(c, pl[0], pl[1], pl[2], pl[3],
                             bh4[sub * 2], bh4[sub * 2 + 1]);
                }
            }
        }
    }

    /* ---- epilogue: normalize, write tf32-rounded ao ---- */
    const float i0 = 1.f / lrow0;
    const float i1 = 1.f / lrow1;
    const int r0 = qt * 128 + w * 16 + (lane >> 2);
    const size_t base0 = ((size_t)b * N_ + r0) * D_ + h * DH_ + (lane & 3) * 2;
    const size_t base1 = base0 + 8 * D_;
#pragma unroll
    for (int nt = 0; nt < 8; nt++) {
        float2 v0 = make_float2(o[nt][0] * i0, o[nt][1] * i0);
        float2 v1 = make_float2(o[nt][2] * i1, o[nt][3] * i1);
        asm("cvt.rna.tf32.f32 %0, %1;" : "=r"(*(uint32_t*)&v0.x) : "f"(v0.x));
        asm("cvt.rna.tf32.f32 %0, %1;" : "=r"(*(uint32_t*)&v0.y) : "f"(v0.y));
        asm("cvt.rna.tf32.f32 %0, %1;" : "=r"(*(uint32_t*)&v1.x) : "f"(v1.x));
        asm("cvt.rna.tf32.f32 %0, %1;" : "=r"(*(uint32_t*)&v1.y) : "f"(v1.y));
        *reinterpret_cast<float2*>(g_aor + base0 + nt * 8) = v0;
        *reinterpret_cast<float2*>(g_aor + base1 + nt * 8) = v1;
    }
}

/* ------------------------------------------------------------------ */
extern "C" void kernel_launch(void* const* d_in, const int* in_sizes, int n_in,
                              void* d_out, int out_size)
{
    const float* x    = (const float*)d_in[0];
    /* d_in[1] = mask (static causal structure, unused) */
    const float* Wqkv = (const float*)d_in[2];
    const float* Wout = (const float*)d_in[3];
    float* out = (float*)d_out;

    float *xr, *wqr, *wor, *aor;
    cudaGetSymbolAddress((void**)&xr,  g_xr);
    cudaGetSymbolAddress((void**)&wqr, g_wqr);
    cudaGetSymbolAddress((void**)&wor, g_wor);
    cudaGetSymbolAddress((void**)&aor, g_aor);

    /* 0. pre-round inputs to tf32 (rna) */
    round_tf32<<<1024, 256>>>(x,    xr,  4096 * 1024 / 4);
    round_tf32<<<1024, 256>>>(Wqkv, wqr, 3072 * 1024 / 4);
    round_tf32<<<512,  256>>>(Wout, wor, 1024 * 1024 / 4);

    cudaFuncSetAttribute(gemm_tf32<0>,
                         cudaFuncAttributeMaxDynamicSharedMemorySize, GEMM_SMEM);
    cudaFuncSetAttribute(gemm_tf32<1>,
                         cudaFuncAttributeMaxDynamicSharedMemorySize, GEMM_SMEM);

    /* 1. QKV projection (tf32) -> q/k/v bf16 hi/lo (q pre-scaled) */
    gemm_tf32<0><<<dim3(3072 / 128, 4096 / 256), 512, GEMM_SMEM>>>(
        xr, wqr, nullptr, D_, 3 * D_);

    /* 2. causal flash attention (bf16 hi/lo) -> tf32-rounded ao */
    const int ATT_SMEM = ATT_SMEM_ELEMS * (int)sizeof(__nv_bfloat16);
    cudaFuncSetAttribute(attn_mma,
                         cudaFuncAttributeMaxDynamicSharedMemorySize, ATT_SMEM);
    attn_mma<<<dim3((N_ / 128) * 32), 256, ATT_SMEM>>>();

    /* 3. output projection (tf32) -> d_out (fp32) */
    gemm_tf32<1><<<dim3(1024 / 128, 4096 / 256), 512, GEMM_SMEM>>>(
        aor, wor, out, D_, D_);
}

// round 13
// speedup vs baseline: 1.0549x; 1.0549x over previous
#include <cuda_runtime.h>
#include <cuda_bf16.h>
#include <math.h>
#include <stdint.h>

#define B_ 2
#define N_ 2048
#define D_ 1024
#define H_ 16
#define DH_ 64
#define SCALE_ 0.125f   /* 64^-0.5, exact power of two */

/* ------------------------------------------------------------------ */
/* device scratch                                                      */
/* ------------------------------------------------------------------ */
__device__ float g_xr [4096 * 1024];   /* tf32-rounded x      */
__device__ float g_wqr[3072 * 1024];   /* tf32-rounded W_qkv  */
__device__ float g_wor[1024 * 1024];   /* tf32-rounded W_out  */
__device__ __nv_bfloat16 g_qh[B_*H_*N_*DH_], g_ql[B_*H_*N_*DH_];
__device__ __nv_bfloat16 g_kh[B_*H_*N_*DH_], g_kl[B_*H_*N_*DH_];
__device__ __nv_bfloat16 g_vh[B_*H_*N_*DH_], g_vl[B_*H_*N_*DH_];
__device__ float         g_aor[B_*N_*D_];  /* tf32-rounded ao */

/* ------------------------------------------------------------------ */
/* helpers                                                             */
/* ------------------------------------------------------------------ */
__device__ __forceinline__ uint32_t smem_u32(const void* p) {
    uint32_t a;
    asm("{ .reg .u64 t; cvta.to.shared.u64 t, %1; cvt.u32.u64 %0, t; }"
        : "=r"(a) : "l"(p));
    return a;
}

/* swizzle for 128B-row fp32 tiles: chunk' = chunk ^ (row & 7) */
__device__ __forceinline__ uint32_t swzA(uint32_t o) {
    return o ^ (((o >> 7) & 7u) << 4);
}

__device__ __forceinline__ void ldsm4(uint32_t addr, uint32_t& r0, uint32_t& r1,
                                      uint32_t& r2, uint32_t& r3) {
    asm volatile("ldmatrix.sync.aligned.m8n8.x4.shared.b16 {%0,%1,%2,%3}, [%4];"
                 : "=r"(r0), "=r"(r1), "=r"(r2), "=r"(r3) : "r"(addr));
}

__device__ __forceinline__ void ldsm4t(uint32_t addr, uint32_t& r0, uint32_t& r1,
                                       uint32_t& r2, uint32_t& r3) {
    asm volatile("ldmatrix.sync.aligned.m8n8.x4.trans.shared.b16 {%0,%1,%2,%3}, [%4];"
                 : "=r"(r0), "=r"(r1), "=r"(r2), "=r"(r3) : "r"(addr));
}

__device__ __forceinline__ void mma16816(float* c,
                                         uint32_t a0, uint32_t a1, uint32_t a2, uint32_t a3,
                                         uint32_t b0, uint32_t b1) {
    asm volatile(
        "mma.sync.aligned.m16n8k16.row.col.f32.bf16.bf16.f32 "
        "{%0,%1,%2,%3}, {%4,%5,%6,%7}, {%8,%9}, {%0,%1,%2,%3};"
        : "+f"(c[0]), "+f"(c[1]), "+f"(c[2]), "+f"(c[3])
        : "r"(a0), "r"(a1), "r"(a2), "r"(a3), "r"(b0), "r"(b1));
}

__device__ __forceinline__ void mma_tf32(float* c,
                                         uint32_t a0, uint32_t a1, uint32_t a2, uint32_t a3,
                                         uint32_t b0, uint32_t b1) {
    asm volatile(
        "mma.sync.aligned.m16n8k8.row.col.f32.tf32.tf32.f32 "
        "{%0,%1,%2,%3}, {%4,%5,%6,%7}, {%8,%9}, {%0,%1,%2,%3};"
        : "+f"(c[0]), "+f"(c[1]), "+f"(c[2]), "+f"(c[3])
        : "r"(a0), "r"(a1), "r"(a2), "r"(a3), "r"(b0), "r"(b1));
}

__device__ __forceinline__ void split2(float x, float y, uint32_t& hi, uint32_t& lo) {
    __nv_bfloat162 h = __floats2bfloat162_rn(x, y);
    float rx = x - __bfloat162float(h.x);
    float ry = y - __bfloat162float(h.y);
    __nv_bfloat162 l = __floats2bfloat162_rn(rx, ry);
    hi = *reinterpret_cast<uint32_t*>(&h);
    lo = *reinterpret_cast<uint32_t*>(&l);
}

__device__ __forceinline__ void cp16(uint32_t saddr, const void* g) {
    asm volatile("cp.async.cg.shared.global [%0], [%1], 16;"
                 :: "r"(saddr), "l"(g) : "memory");
}

/* ---- mbarrier primitives (sm_90 generic) ---- */
__device__ __forceinline__ void mbar_init(uint32_t a, uint32_t cnt) {
    asm volatile("mbarrier.init.shared.b64 [%0], %1;" :: "r"(a), "r"(cnt) : "memory");
}
__device__ __forceinline__ void mbar_arrive(uint32_t a) {
    asm volatile("mbarrier.arrive.shared.b64 _, [%0];" :: "r"(a) : "memory");
}
__device__ __forceinline__ void cp_arrive(uint32_t a) {
    asm volatile("cp.async.mbarrier.arrive.noinc.shared.b64 [%0];"
                 :: "r"(a) : "memory");
}
__device__ __forceinline__ void mbar_wait(uint32_t a, uint32_t parity) {
    asm volatile(
        "{\n\t.reg .pred P;\n"
        "W_%=:\n\t"
        "mbarrier.try_wait.parity.acquire.cta.shared::cta.b64 P, [%0], %1;\n\t"
        "@P bra D_%=;\n\t"
        "bra W_%=;\n"
        "D_%=:\n\t}"
        :: "r"(a), "r"(parity) : "memory");
}

/* ------------------------------------------------------------------ */
/* round kernel: fp32 -> tf32-rounded fp32 (rna)                       */
/* ------------------------------------------------------------------ */
__global__ void __launch_bounds__(256)
round_tf32(const float* __restrict__ src, float* __restrict__ dst, int n4)
{
    int i      = blockIdx.x * blockDim.x + threadIdx.x;
    int stride = gridDim.x * blockDim.x;
    for (; i < n4; i += stride) {
        float4 v = reinterpret_cast<const float4*>(src)[i];
        float4 r;
        asm("cvt.rna.tf32.f32 %0, %1;" : "=r"(*(uint32_t*)&r.x) : "f"(v.x));
        asm("cvt.rna.tf32.f32 %0, %1;" : "=r"(*(uint32_t*)&r.y) : "f"(v.y));
        asm("cvt.rna.tf32.f32 %0, %1;" : "=r"(*(uint32_t*)&r.z) : "f"(v.z));
        asm("cvt.rna.tf32.f32 %0, %1;" : "=r"(*(uint32_t*)&r.w) : "f"(v.w));
        reinterpret_cast<float4*>(dst)[i] = r;
    }
}

/* ------------------------------------------------------------------ */
/* TF32 HMMA GEMM on pre-rounded fp32: C = A * W^T.                    */
/* tile 128x128, BK=32, 256 thr (8 warps 4x2), 2 CTAs/SM.              */
/* 3-stage mbarrier full/empty pipeline (no __syncthreads in loop).    */
/* MODE 0: epilogue -> q/k/v bf16 hi/lo (q scaled). MODE 1: fp32 C.    */
/* ------------------------------------------------------------------ */
#define GARR_B (128 * 128u)                 /* bytes per fp32 array (16 KB) */
#define GSTAGE_B (2 * GARR_B)               /* bytes per stage (32 KB)      */
#define GEMM_SMEM (128 + 3 * GSTAGE_B)      /* 98432 B dynamic              */

template <int MODE>
__global__ void __launch_bounds__(256, 2)
gemm_tf32(const float* __restrict__ A, const float* __restrict__ W,
          float* __restrict__ C, int K, int Nout)
{
    extern __shared__ float smem[];
    const uint32_t sb = smem_u32(smem);
    /* mbarriers: full[3] at sb+0,8,16 ; empty[3] at sb+24,32,40 */
    const uint32_t MBF = sb;
    const uint32_t MBE = sb + 24;
    const uint32_t DB  = sb + 128;          /* data base */

    const int tid  = threadIdx.x;
    const int lane = tid & 31;
    const int wid  = tid >> 5;
    const int wm   = wid & 3;
    const int wn   = wid >> 2;

    const int m0 = blockIdx.y * 128;
    const int j0 = blockIdx.x * 128;

    if (tid == 0) {
#pragma unroll
        for (int s = 0; s < 3; s++) {
            mbar_init(MBF + s * 8, 256);
            mbar_init(MBE + s * 8, 256);
        }
    }
    __syncthreads();

    const int q0 = tid & 7;

#define ISSUE_CHUNK(kc, stage)                                                \
    do {                                                                      \
        const int koff = (kc) * 32;                                          \
        const uint32_t st_ = DB + (uint32_t)(stage) * GSTAGE_B;              \
        _Pragma("unroll")                                                     \
        for (int i_ = 0; i_ < 4; i_++) {                                     \
            int r_ = (tid + i_ * 256) >> 3;                                  \
            uint32_t so_ = swzA((uint32_t)(r_ * 128 + q0 * 16));             \
            cp16(st_ + so_,          A + (size_t)(m0 + r_) * K + koff + q0 * 4); \
            cp16(st_ + GARR_B + so_, W + (size_t)(j0 + r_) * K + koff + q0 * 4); \
        }                                                                     \
        cp_arrive(MBF + (stage) * 8);                                        \
    } while (0)

    /* ldsm lane address components */
    const int a_r8 = lane & 7;
    const int a_rh = (lane >> 3) & 1;
    const int a_ch = lane >> 4;
    const int b_rh = lane >> 4;
    const int b_ch = (lane >> 3) & 1;

    float acc[2][8][4];
#pragma unroll
    for (int i = 0; i < 2; i++)
#pragma unroll
        for (int j = 0; j < 8; j++)
#pragma unroll
            for (int c = 0; c < 4; c++) acc[i][j][c] = 0.f;

    const int nchunk = K >> 5;   /* 32 */

    ISSUE_CHUNK(0, 0);
    ISSUE_CHUNK(1, 1);

    for (int kc = 0; kc < nchunk; kc++) {
        const int s = kc - (kc / 3) * 3;          /* kc % 3 */
        /* issue chunk kc+2 into stage (kc+2)%3 == (kc-1)%3 */
        if (kc + 2 < nchunk) {
            const int s2 = (kc + 2) - ((kc + 2) / 3) * 3;
            if (kc >= 1) mbar_wait(MBE + s2 * 8, (uint32_t)(((kc - 1) / 3) & 1));
            ISSUE_CHUNK(kc + 2, s2);
        }

        mbar_wait(MBF + s * 8, (uint32_t)((kc / 3) & 1));

        const uint32_t stg = DB + (uint32_t)s * GSTAGE_B;
        const uint32_t sA  = stg;
        const uint32_t sW  = stg + GARR_B;

#pragma unroll
        for (int ks = 0; ks < 4; ks++) {       /* k8 steps within BK=32 */
            uint32_t a[2][4];
#pragma unroll
            for (int mt = 0; mt < 2; mt++) {
                int row   = wm * 32 + mt * 16 + a_r8 + a_rh * 8;
                int chunk = ks * 2 + a_ch;
                uint32_t addr = sA + swzA((uint32_t)(row * 128 + chunk * 16));
                ldsm4(addr, a[mt][0], a[mt][1], a[mt][2], a[mt][3]);
            }
#pragma unroll
            for (int np = 0; np < 4; np++) {
                int row   = wn * 64 + np * 16 + a_r8 + b_rh * 8;
                int chunk = ks * 2 + b_ch;
                uint32_t addr = sW + swzA((uint32_t)(row * 128 + chunk * 16));
                uint32_t bfr[4];
                ldsm4(addr, bfr[0], bfr[1], bfr[2], bfr[3]);
#pragma unroll
                for (int mt = 0; mt < 2; mt++) {
                    mma_tf32(acc[mt][np * 2 + 0], a[mt][0], a[mt][1], a[mt][2], a[mt][3],
                             bfr[0], bfr[1]);
                    mma_tf32(acc[mt][np * 2 + 1], a[mt][0], a[mt][1], a[mt][2], a[mt][3],
                             bfr[2], bfr[3]);
                }
            }
        }
        mbar_arrive(MBE + s * 8);
    }

    /* epilogue */
    const int grp = lane >> 2;
    const int qid = lane & 3;
#pragma unroll
    for (int mt = 0; mt < 2; mt++) {
#pragma unroll
        for (int nt = 0; nt < 8; nt++) {
            const float* c = acc[mt][nt];
            int row = m0 + wm * 32 + mt * 16 + grp;
            int col = j0 + wn * 64 + nt * 8 + qid * 2;
#pragma unroll
            for (int half = 0; half < 2; half++) {
                int m = row + half * 8;
                float vx = c[half * 2], vy = c[half * 2 + 1];
                if (MODE == 0) {
                    int s  = col >> 10;
                    int rr = col & 1023;
                    int h  = rr >> 6;
                    int dh = rr & 63;
                    int b  = m >> 11;
                    int n  = m & 2047;
                    size_t idx = (((size_t)(b * H_ + h) * N_ + n) * DH_ + dh);
                    float sc = (s == 0) ? SCALE_ : 1.f;
                    uint32_t hi, lo;
                    split2(vx * sc, vy * sc, hi, lo);
                    __nv_bfloat16* bhp = (s == 0) ? g_qh : (s == 1) ? g_kh : g_vh;
                    __nv_bfloat16* blp = (s == 0) ? g_ql : (s == 1) ? g_kl : g_vl;
                    *reinterpret_cast<uint32_t*>(bhp + idx) = hi;
                    *reinterpret_cast<uint32_t*>(blp + idx) = lo;
                } else {
                    *reinterpret_cast<float2*>(C + (size_t)m * Nout + col) =
                        make_float2(vx, vy);
                }
            }
        }
    }
}

/* ------------------------------------------------------------------ */
/* Flash-attention (bf16 hi/lo). 2-stage KV pipeline on mbarriers.     */
/* V fragments via ldmatrix.trans. 2 CTAs/SM. Epilogue: tf32 ao.       */
/* ------------------------------------------------------------------ */
#define ASTR 72
#define QOFF 64                               /* elements: 128 B for mbarriers */
#define SM_QH 0
#define SM_QL (128 * ASTR)
#define SM_ST0 (2 * 128 * ASTR)
#define STG_E  (4 * 64 * ASTR)
#define OFF_KH 0
#define OFF_KL (64 * ASTR)
#define OFF_VH (2 * 64 * ASTR)
#define OFF_VL (3 * 64 * ASTR)
#define ATT_SMEM_BYTES (128 + (SM_ST0 + 2 * STG_E) * 2)   /* 110720 B */

__global__ void __launch_bounds__(256, 2)
attn_mma()
{
    extern __shared__ __nv_bfloat16 sbuf_raw[];
    __nv_bfloat16* sbuf = sbuf_raw + QOFF;     /* data region */

    const uint32_t sb0 = smem_u32(sbuf_raw);
    /* mbarriers: full[2] at +0,+8 ; empty[2] at +16,+24 */
    const uint32_t MBF = sb0;
    const uint32_t MBE = sb0 + 16;
    const uint32_t sB  = sb0 + 128;            /* data base (byte addr) */

    const int qt = (N_ / 128 - 1) - (blockIdx.x >> 5);  /* heavy tiles first */
    const int bh = blockIdx.x & 31;
    const int b  = bh >> 4;
    const int h  = bh & 15;

    const int tid  = threadIdx.x;
    const int lane = tid & 31;
    const int w    = tid >> 5;

    const __nv_bfloat16* Qbh = g_qh + (size_t)bh * N_ * DH_;
    const __nv_bfloat16* Qbl = g_ql + (size_t)bh * N_ * DH_;
    const __nv_bfloat16* Kbh = g_kh + (size_t)bh * N_ * DH_;
    const __nv_bfloat16* Kbl = g_kl + (size_t)bh * N_ * DH_;
    const __nv_bfloat16* Vbh = g_vh + (size_t)bh * N_ * DH_;
    const __nv_bfloat16* Vbl = g_vl + (size_t)bh * N_ * DH_;

    if (tid == 0) {
#pragma unroll
        for (int s = 0; s < 2; s++) {
            mbar_init(MBF + s * 8, 256);
            mbar_init(MBE + s * 8, 256);
        }
    }
    __syncthreads();

    const int kr0 = tid >> 3;
    const int kr1 = (tid + 256) >> 3;
    const int kc8 = (tid & 7) * 8;
    const uint32_t kso0 = (uint32_t)(kr0 * ASTR + kc8) * 2;
    const uint32_t kso1 = (uint32_t)(kr1 * ASTR + kc8) * 2;

#define ISSUE_KV(jt, stage)                                                   \
    do {                                                                      \
        const size_t g0 = (size_t)((jt) * 64 + kr0) * DH_ + kc8;             \
        const size_t g1 = (size_t)((jt) * 64 + kr1) * DH_ + kc8;             \
        const uint32_t st_ = sB + (SM_ST0 + (stage) * STG_E) * 2;            \
        cp16(st_ + OFF_KH * 2 + kso0, Kbh + g0);                             \
        cp16(st_ + OFF_KH * 2 + kso1, Kbh + g1);                             \
        cp16(st_ + OFF_KL * 2 + kso0, Kbl + g0);                             \
        cp16(st_ + OFF_KL * 2 + kso1, Kbl + g1);                             \
        cp16(st_ + OFF_VH * 2 + kso0, Vbh + g0);                             \
        cp16(st_ + OFF_VH * 2 + kso1, Vbh + g1);                             \
        cp16(st_ + OFF_VL * 2 + kso0, Vbl + g0);                             \
        cp16(st_ + OFF_VL * 2 + kso1, Vbl + g1);                             \
        cp_arrive(MBF + (stage) * 8);                                        \
    } while (0)

    ISSUE_KV(0, 0);

    /* ---- load Q tile (pre-scaled, pre-split) ---- */
#pragma unroll
    for (int it = 0; it < 4; it++) {
        int idx = tid + it * 256;
        int r   = idx >> 3;
        int c8  = (idx & 7) * 8;
        size_t g = (size_t)(qt * 128 + r) * DH_ + c8;
        *reinterpret_cast<uint4*>(sbuf + SM_QH + r * ASTR + c8) =
            *reinterpret_cast<const uint4*>(Qbh + g);
        *reinterpret_cast<uint4*>(sbuf + SM_QL + r * ASTR + c8) =
            *reinterpret_cast<const uint4*>(Qbl + g);
    }
    __syncthreads();

    /* ---- Q fragments into registers ---- */
    uint32_t qh[4][4], ql[4][4];
    {
        const uint32_t a0 = sB +
            2u * ((uint32_t)((w * 16 + (lane & 15)) * ASTR) + ((lane >> 4) << 3));
#pragma unroll
        for (int ks = 0; ks < 4; ks++) {
            ldsm4(a0 + SM_QH * 2 + 2u * (ks * 16),
                  qh[ks][0], qh[ks][1], qh[ks][2], qh[ks][3]);
            ldsm4(a0 + SM_QL * 2 + 2u * (ks * 16),
                  ql[ks][0], ql[ks][1], ql[ks][2], ql[ks][3]);
        }
    }

    const uint32_t bpat = 2u * ((uint32_t)(((lane & 7) | ((lane & 16) >> 1)) * ASTR)
                                + (lane & 8));
    const uint32_t vpat = 2u * ((uint32_t)((lane & 15) * ASTR) + ((lane & 16) >> 1));

    float o[8][4];
#pragma unroll
    for (int i = 0; i < 8; i++)
#pragma unroll
        for (int c = 0; c < 4; c++) o[i][c] = 0.f;
    float mrow0 = -INFINITY, mrow1 = -INFINITY;
    float lrow0 = 0.f, lrow1 = 0.f;

    const int qglo   = qt * 128 + w * 16;
    const int ntiles = 2 * qt + 2;

    for (int jt = 0; jt < ntiles; jt++) {
        const int s = jt & 1;
        /* issue tile jt+1 into stage (jt+1)&1 (prior user: tile jt-1) */
        if (jt + 1 < ntiles) {
            const int s2 = (jt + 1) & 1;
            if (jt >= 1) mbar_wait(MBE + s2 * 8, (uint32_t)(((jt - 1) >> 1) & 1));
            ISSUE_KV(jt + 1, s2);
        }

        mbar_wait(MBF + s * 8, (uint32_t)((jt >> 1) & 1));

        if (jt * 64 <= qglo + 15) {            /* warp has work this tile */
            const uint32_t stg = sB + (SM_ST0 + s * STG_E) * 2;
            const uint32_t sKH = stg + OFF_KH * 2;
            const uint32_t sKL = stg + OFF_KL * 2;
            const uint32_t sVH = stg + OFF_VH * 2;
            const uint32_t sVL = stg + OFF_VL * 2;

            /* ---- S = Q K^T ---- */
            float sfr[8][4];
#pragma unroll
            for (int i = 0; i < 8; i++)
#pragma unroll
                for (int c = 0; c < 4; c++) sfr[i][c] = 0.f;

#pragma unroll
            for (int ks = 0; ks < 4; ks++) {
#pragma unroll
                for (int np = 0; np < 4; np++) {
                    const uint32_t boff = bpat + 2u * (np * 16 * ASTR + ks * 16);
                    uint32_t bh4[4], bl4[4];
                    ldsm4(sKH + boff, bh4[0], bh4[1], bh4[2], bh4[3]);
                    ldsm4(sKL + boff, bl4[0], bl4[1], bl4[2], bl4[3]);
#pragma unroll
                    for (int sub = 0; sub < 2; sub++) {
                        float* c = sfr[np * 2 + sub];
                        mma16816(c, qh[ks][0], qh[ks][1], qh[ks][2], qh[ks][3],
                                 bh4[sub * 2], bh4[sub * 2 + 1]);
                        mma16816(c, qh[ks][0], qh[ks][1], qh[ks][2], qh[ks][3],
                                 bl4[sub * 2], bl4[sub * 2 + 1]);
                        mma16816(c, ql[ks][0], ql[ks][1], ql[ks][2], ql[ks][3],
                                 bh4[sub * 2], bh4[sub * 2 + 1]);
                    }
                }
            }

            /* ---- causal mask ---- */
            const int r0 = qglo + (lane >> 2);
            const int r1 = r0 + 8;
            if (jt * 64 + 63 > qglo) {
                const int colb = jt * 64 + (lane & 3) * 2;
#pragma unroll
                for (int nt = 0; nt < 8; nt++) {
                    int c0 = colb + nt * 8;
                    if (c0 > r0)     sfr[nt][0] = -INFINITY;
                    if (c0 + 1 > r0) sfr[nt][1] = -INFINITY;
                    if (c0 > r1)     sfr[nt][2] = -INFINITY;
                    if (c0 + 1 > r1) sfr[nt][3] = -INFINITY;
                }
            }

            /* ---- online softmax ---- */
            float mt0 = sfr[0][0], mt1 = sfr[0][2];
#pragma unroll
            for (int nt = 0; nt < 8; nt++) {
                mt0 = fmaxf(mt0, fmaxf(sfr[nt][0], sfr[nt][1]));
                mt1 = fmaxf(mt1, fmaxf(sfr[nt][2], sfr[nt][3]));
            }
            mt0 = fmaxf(mt0, __shfl_xor_sync(0xffffffffu, mt0, 1));
            mt0 = fmaxf(mt0, __shfl_xor_sync(0xffffffffu, mt0, 2));
            mt1 = fmaxf(mt1, __shfl_xor_sync(0xffffffffu, mt1, 1));
            mt1 = fmaxf(mt1, __shfl_xor_sync(0xffffffffu, mt1, 2));

            const float mn0 = fmaxf(mrow0, mt0);
            const float mn1 = fmaxf(mrow1, mt1);
            const float al0 = __expf(mrow0 - mn0);
            const float al1 = __expf(mrow1 - mn1);

            float ps0 = 0.f, ps1 = 0.f;
#pragma unroll
            for (int nt = 0; nt < 8; nt++) {
                sfr[nt][0] = __expf(sfr[nt][0] - mn0);
                sfr[nt][1] = __expf(sfr[nt][1] - mn0);
                sfr[nt][2] = __expf(sfr[nt][2] - mn1);
                sfr[nt][3] = __expf(sfr[nt][3] - mn1);
                ps0 += sfr[nt][0] + sfr[nt][1];
                ps1 += sfr[nt][2] + sfr[nt][3];
            }
            ps0 += __shfl_xor_sync(0xffffffffu, ps0, 1);
            ps0 += __shfl_xor_sync(0xffffffffu, ps0, 2);
            ps1 += __shfl_xor_sync(0xffffffffu, ps1, 1);
            ps1 += __shfl_xor_sync(0xffffffffu, ps1, 2);

            lrow0 = lrow0 * al0 + ps0;
            lrow1 = lrow1 * al1 + ps1;
#pragma unroll
            for (int nt = 0; nt < 8; nt++) {
                o[nt][0] *= al0; o[nt][1] *= al0;
                o[nt][2] *= al1; o[nt][3] *= al1;
            }
            mrow0 = mn0;
            mrow1 = mn1;

            /* ---- O += P V (V fragments via ldmatrix.trans) ---- */
#pragma unroll
            for (int ks = 0; ks < 4; ks++) {
                uint32_t ph[4], pl[4];
                split2(sfr[2 * ks][0],     sfr[2 * ks][1],     ph[0], pl[0]);
                split2(sfr[2 * ks][2],     sfr[2 * ks][3],     ph[1], pl[1]);
                split2(sfr[2 * ks + 1][0], sfr[2 * ks + 1][1], ph[2], pl[2]);
                split2(sfr[2 * ks + 1][2], sfr[2 * ks + 1][3], ph[3], pl[3]);
#pragma unroll
                for (int np = 0; np < 4; np++) {
                    const uint32_t voff = vpat + 2u * (ks * 16 * ASTR + np * 16);
                    uint32_t bh4[4], bl4[4];
                    ldsm4t(sVH + voff, bh4[0], bh4[1], bh4[2], bh4[3]);
                    ldsm4t(sVL + voff, bl4[0], bl4[1], bl4[2], bl4[3]);
#pragma unroll
                    for (int sub = 0; sub < 2; sub++) {
                        float* c = o[np * 2 + sub];
                        mma16816(c, ph[0], ph[1], ph[2], ph[3],
                                 bh4[sub * 2], bh4[sub * 2 + 1]);
                        mma16816(c, ph[0], ph[1], ph[2], ph[3],
                                 bl4[sub * 2], bl4[sub * 2 + 1]);
                        mma16816(c, pl[0], pl[1], pl[2], pl[3],
                                 bh4[sub * 2], bh4[sub * 2 + 1]);
                    }
                }
            }
        }

        mbar_arrive(MBE + s * 8);
    }

    /* ---- epilogue: normalize, write tf32-rounded ao ---- */
    const float i0 = 1.f / lrow0;
    const float i1 = 1.f / lrow1;
    const int r0 = qt * 128 + w * 16 + (lane >> 2);
    const size_t base0 = ((size_t)b * N_ + r0) * D_ + h * DH_ + (lane & 3) * 2;
    const size_t base1 = base0 + 8 * D_;
#pragma unroll
    for (int nt = 0; nt < 8; nt++) {
        float2 v0 = make_float2(o[nt][0] * i0, o[nt][1] * i0);
        float2 v1 = make_float2(o[nt][2] * i1, o[nt][3] * i1);
        asm("cvt.rna.tf32.f32 %0, %1;" : "=r"(*(uint32_t*)&v0.x) : "f"(v0.x));
        asm("cvt.rna.tf32.f32 %0, %1;" : "=r"(*(uint32_t*)&v0.y) : "f"(v0.y));
        asm("cvt.rna.tf32.f32 %0, %1;" : "=r"(*(uint32_t*)&v1.x) : "f"(v1.x));
        asm("cvt.rna.tf32.f32 %0, %1;" : "=r"(*(uint32_t*)&v1.y) : "f"(v1.y));
        *reinterpret_cast<float2*>(g_aor + base0 + nt * 8) = v0;
        *reinterpret_cast<float2*>(g_aor + base1 + nt * 8) = v1;
    }
}

/* ------------------------------------------------------------------ */
extern "C" void kernel_launch(void* const* d_in, const int* in_sizes, int n_in,
                              void* d_out, int out_size)
{
    const float* x    = (const float*)d_in[0];
    /* d_in[1] = mask (static causal structure, unused) */
    const float* Wqkv = (const float*)d_in[2];
    const float* Wout = (const float*)d_in[3];
    float* out = (float*)d_out;

    float *xr, *wqr, *wor, *aor;
    cudaGetSymbolAddress((void**)&xr,  g_xr);
    cudaGetSymbolAddress((void**)&wqr, g_wqr);
    cudaGetSymbolAddress((void**)&wor, g_wor);
    cudaGetSymbolAddress((void**)&aor, g_aor);

    /* 0. pre-round inputs to tf32 (rna) */
    round_tf32<<<1024, 256>>>(x,    xr,  4096 * 1024 / 4);
    round_tf32<<<1024, 256>>>(Wqkv, wqr, 3072 * 1024 / 4);
    round_tf32<<<512,  256>>>(Wout, wor, 1024 * 1024 / 4);

    cudaFuncSetAttribute(gemm_tf32<0>,
                         cudaFuncAttributeMaxDynamicSharedMemorySize, GEMM_SMEM);
    cudaFuncSetAttribute(gemm_tf32<1>,
                         cudaFuncAttributeMaxDynamicSharedMemorySize, GEMM_SMEM);

    /* 1. QKV projection (tf32) -> q/k/v bf16 hi/lo (q pre-scaled) */
    gemm_tf32<0><<<dim3(3072 / 128, 4096 / 128), 256, GEMM_SMEM>>>(
        xr, wqr, nullptr, D_, 3 * D_);

    /* 2. causal flash attention (bf16 hi/lo) -> tf32-rounded ao */
    cudaFuncSetAttribute(attn_mma,
                         cudaFuncAttributeMaxDynamicSharedMemorySize, ATT_SMEM_BYTES);
    attn_mma<<<dim3((N_ / 128) * 32), 256, ATT_SMEM_BYTES>>>();

    /* 3. output projection (tf32) -> d_out (fp32) */
    gemm_tf32<1><<<dim3(1024 / 128, 4096 / 128), 256, GEMM_SMEM>>>(
        aor, wor, out, D_, D_);
}

// round 14
// speedup vs baseline: 1.0750x; 1.0191x over previous
#include <cuda_runtime.h>
#include <cuda_bf16.h>
#include <math.h>
#include <stdint.h>

#define B_ 2
#define N_ 2048
#define D_ 1024
#define H_ 16
#define DH_ 64
#define SCALE_ 0.125f   /* 64^-0.5, exact power of two */

/* ------------------------------------------------------------------ */
/* device scratch                                                      */
/* ------------------------------------------------------------------ */
__device__ float g_xr [4096 * 1024];   /* tf32-rounded x      */
__device__ float g_wqr[3072 * 1024];   /* tf32-rounded W_qkv  */
__device__ float g_wor[1024 * 1024];   /* tf32-rounded W_out  */
__device__ __nv_bfloat16 g_qh[B_*H_*N_*DH_], g_ql[B_*H_*N_*DH_];
__device__ __nv_bfloat16 g_kh[B_*H_*N_*DH_], g_kl[B_*H_*N_*DH_];
__device__ __nv_bfloat16 g_vh[B_*H_*N_*DH_], g_vl[B_*H_*N_*DH_];
__device__ float         g_aor[B_*N_*D_];  /* tf32-rounded ao */

/* ------------------------------------------------------------------ */
/* helpers                                                             */
/* ------------------------------------------------------------------ */
__device__ __forceinline__ uint32_t smem_u32(const void* p) {
    uint32_t a;
    asm("{ .reg .u64 t; cvta.to.shared.u64 t, %1; cvt.u32.u64 %0, t; }"
        : "=r"(a) : "l"(p));
    return a;
}

/* swizzle for 128B-row fp32 tiles: chunk' = chunk ^ (row & 7) */
__device__ __forceinline__ uint32_t swzA(uint32_t o) {
    return o ^ (((o >> 7) & 7u) << 4);
}

__device__ __forceinline__ void ldsm4(uint32_t addr, uint32_t& r0, uint32_t& r1,
                                      uint32_t& r2, uint32_t& r3) {
    asm volatile("ldmatrix.sync.aligned.m8n8.x4.shared.b16 {%0,%1,%2,%3}, [%4];"
                 : "=r"(r0), "=r"(r1), "=r"(r2), "=r"(r3) : "r"(addr));
}

__device__ __forceinline__ void ldsm4t(uint32_t addr, uint32_t& r0, uint32_t& r1,
                                       uint32_t& r2, uint32_t& r3) {
    asm volatile("ldmatrix.sync.aligned.m8n8.x4.trans.shared.b16 {%0,%1,%2,%3}, [%4];"
                 : "=r"(r0), "=r"(r1), "=r"(r2), "=r"(r3) : "r"(addr));
}

__device__ __forceinline__ void mma16816(float* c,
                                         uint32_t a0, uint32_t a1, uint32_t a2, uint32_t a3,
                                         uint32_t b0, uint32_t b1) {
    asm volatile(
        "mma.sync.aligned.m16n8k16.row.col.f32.bf16.bf16.f32 "
        "{%0,%1,%2,%3}, {%4,%5,%6,%7}, {%8,%9}, {%0,%1,%2,%3};"
        : "+f"(c[0]), "+f"(c[1]), "+f"(c[2]), "+f"(c[3])
        : "r"(a0), "r"(a1), "r"(a2), "r"(a3), "r"(b0), "r"(b1));
}

__device__ __forceinline__ void mma_tf32(float* c,
                                         uint32_t a0, uint32_t a1, uint32_t a2, uint32_t a3,
                                         uint32_t b0, uint32_t b1) {
    asm volatile(
        "mma.sync.aligned.m16n8k8.row.col.f32.tf32.tf32.f32 "
        "{%0,%1,%2,%3}, {%4,%5,%6,%7}, {%8,%9}, {%0,%1,%2,%3};"
        : "+f"(c[0]), "+f"(c[1]), "+f"(c[2]), "+f"(c[3])
        : "r"(a0), "r"(a1), "r"(a2), "r"(a3), "r"(b0), "r"(b1));
}

__device__ __forceinline__ void split2(float x, float y, uint32_t& hi, uint32_t& lo) {
    __nv_bfloat162 h = __floats2bfloat162_rn(x, y);
    float rx = x - __bfloat162float(h.x);
    float ry = y - __bfloat162float(h.y);
    __nv_bfloat162 l = __floats2bfloat162_rn(rx, ry);
    hi = *reinterpret_cast<uint32_t*>(&h);
    lo = *reinterpret_cast<uint32_t*>(&l);
}

__device__ __forceinline__ void cp16(uint32_t saddr, const void* g) {
    asm volatile("cp.async.cg.shared.global [%0], [%1], 16;"
                 :: "r"(saddr), "l"(g) : "memory");
}

/* ---- mbarrier primitives (sm_90 generic) ---- */
__device__ __forceinline__ void mbar_init(uint32_t a, uint32_t cnt) {
    asm volatile("mbarrier.init.shared.b64 [%0], %1;" :: "r"(a), "r"(cnt) : "memory");
}
__device__ __forceinline__ void mbar_arrive(uint32_t a) {
    asm volatile("mbarrier.arrive.shared.b64 _, [%0];" :: "r"(a) : "memory");
}
__device__ __forceinline__ void cp_arrive(uint32_t a) {
    asm volatile("cp.async.mbarrier.arrive.noinc.shared.b64 [%0];"
                 :: "r"(a) : "memory");
}
__device__ __forceinline__ void mbar_wait(uint32_t a, uint32_t parity) {
    asm volatile(
        "{\n\t.reg .pred P;\n"
        "W_%=:\n\t"
        "mbarrier.try_wait.parity.acquire.cta.shared::cta.b64 P, [%0], %1;\n\t"
        "@P bra D_%=;\n\t"
        "bra W_%=;\n"
        "D_%=:\n\t}"
        :: "r"(a), "r"(parity) : "memory");
}

/* ------------------------------------------------------------------ */
/* round kernel: fp32 -> tf32-rounded fp32 (rna)                       */
/* ------------------------------------------------------------------ */
__global__ void __launch_bounds__(256)
round_tf32(const float* __restrict__ src, float* __restrict__ dst, int n4)
{
    int i      = blockIdx.x * blockDim.x + threadIdx.x;
    int stride = gridDim.x * blockDim.x;
    for (; i < n4; i += stride) {
        float4 v = reinterpret_cast<const float4*>(src)[i];
        float4 r;
        asm("cvt.rna.tf32.f32 %0, %1;" : "=r"(*(uint32_t*)&r.x) : "f"(v.x));
        asm("cvt.rna.tf32.f32 %0, %1;" : "=r"(*(uint32_t*)&r.y) : "f"(v.y));
        asm("cvt.rna.tf32.f32 %0, %1;" : "=r"(*(uint32_t*)&r.z) : "f"(v.z));
        asm("cvt.rna.tf32.f32 %0, %1;" : "=r"(*(uint32_t*)&r.w) : "f"(v.w));
        reinterpret_cast<float4*>(dst)[i] = r;
    }
}

/* ------------------------------------------------------------------ */
/* TF32 HMMA GEMM on pre-rounded fp32: C = A * W^T.                    */
/* CTA tile 256x128, BK=32, 512 thr (16 warps 4x4), warp tile 64x32.   */
/* 3-stage mbarrier full/empty pipeline (no __syncthreads in loop).    */
/* MODE 0: epilogue -> q/k/v bf16 hi/lo (q scaled). MODE 1: fp32 C.    */
/* ------------------------------------------------------------------ */
#define GARR_A (256 * 128u)                 /* A stage bytes (32 KB)  */
#define GARR_W (128 * 128u)                 /* W stage bytes (16 KB)  */
#define GSTAGE_B (GARR_A + GARR_W)          /* 48 KB per stage        */
#define GEMM_SMEM (128 + 3 * GSTAGE_B)      /* 147584 B dynamic       */

template <int MODE>
__global__ void __launch_bounds__(512, 1)
gemm_tf32(const float* __restrict__ A, const float* __restrict__ W,
          float* __restrict__ C, int K, int Nout)
{
    extern __shared__ float smem[];
    const uint32_t sb = smem_u32(smem);
    /* mbarriers: full[3] at sb+0,8,16 ; empty[3] at sb+24,32,40 */
    const uint32_t MBF = sb;
    const uint32_t MBE = sb + 24;
    const uint32_t DB  = sb + 128;          /* data base */

    const int tid  = threadIdx.x;
    const int lane = tid & 31;
    const int wid  = tid >> 5;        /* 0..15 */
    const int wm   = wid & 3;         /* 64-row slice   */
    const int wn   = wid >> 2;        /* 32-col slice   */

    const int m0 = blockIdx.y * 256;
    const int j0 = blockIdx.x * 128;

    if (tid == 0) {
#pragma unroll
        for (int s = 0; s < 3; s++) {
            mbar_init(MBF + s * 8, 512);
            mbar_init(MBE + s * 8, 512);
        }
    }
    __syncthreads();

    const int q0 = tid & 7;

#define ISSUE_CHUNK(kc, stage)                                                \
    do {                                                                      \
        const int koff = (kc) * 32;                                          \
        const uint32_t st_ = DB + (uint32_t)(stage) * GSTAGE_B;              \
        _Pragma("unroll")                                                     \
        for (int i_ = 0; i_ < 4; i_++) {                                     \
            int r_ = (tid + i_ * 512) >> 3;                                  \
            uint32_t so_ = swzA((uint32_t)(r_ * 128 + q0 * 16));             \
            cp16(st_ + so_, A + (size_t)(m0 + r_) * K + koff + q0 * 4);      \
        }                                                                     \
        _Pragma("unroll")                                                     \
        for (int i_ = 0; i_ < 2; i_++) {                                     \
            int r_ = (tid + i_ * 512) >> 3;                                  \
            uint32_t so_ = swzA((uint32_t)(r_ * 128 + q0 * 16));             \
            cp16(st_ + GARR_A + so_, W + (size_t)(j0 + r_) * K + koff + q0 * 4); \
        }                                                                     \
        cp_arrive(MBF + (stage) * 8);                                        \
    } while (0)

    /* ldsm lane address components */
    const int a_r8 = lane & 7;
    const int a_rh = (lane >> 3) & 1;
    const int a_ch = lane >> 4;
    const int b_rh = lane >> 4;
    const int b_ch = (lane >> 3) & 1;

    float acc[4][4][4];
#pragma unroll
    for (int i = 0; i < 4; i++)
#pragma unroll
        for (int j = 0; j < 4; j++)
#pragma unroll
            for (int c = 0; c < 4; c++) acc[i][j][c] = 0.f;

    const int nchunk = K >> 5;   /* 32 */

    ISSUE_CHUNK(0, 0);
    ISSUE_CHUNK(1, 1);

    for (int kc = 0; kc < nchunk; kc++) {
        const int s = kc - (kc / 3) * 3;          /* kc % 3 */
        if (kc + 2 < nchunk) {
            const int s2 = (kc + 2) - ((kc + 2) / 3) * 3;
            if (kc >= 1) mbar_wait(MBE + s2 * 8, (uint32_t)(((kc - 1) / 3) & 1));
            ISSUE_CHUNK(kc + 2, s2);
        }

        mbar_wait(MBF + s * 8, (uint32_t)((kc / 3) & 1));

        const uint32_t stg = DB + (uint32_t)s * GSTAGE_B;
        const uint32_t sA  = stg;
        const uint32_t sW  = stg + GARR_A;

#pragma unroll
        for (int ks = 0; ks < 4; ks++) {       /* k8 steps within BK=32 */
            uint32_t a[4][4];
#pragma unroll
            for (int mt = 0; mt < 4; mt++) {
                int row   = wm * 64 + mt * 16 + a_r8 + a_rh * 8;
                int chunk = ks * 2 + a_ch;
                uint32_t addr = sA + swzA((uint32_t)(row * 128 + chunk * 16));
                ldsm4(addr, a[mt][0], a[mt][1], a[mt][2], a[mt][3]);
            }
#pragma unroll
            for (int np = 0; np < 2; np++) {
                int row   = wn * 32 + np * 16 + a_r8 + b_rh * 8;
                int chunk = ks * 2 + b_ch;
                uint32_t addr = sW + swzA((uint32_t)(row * 128 + chunk * 16));
                uint32_t bfr[4];
                ldsm4(addr, bfr[0], bfr[1], bfr[2], bfr[3]);
#pragma unroll
                for (int mt = 0; mt < 4; mt++) {
                    mma_tf32(acc[mt][np * 2 + 0], a[mt][0], a[mt][1], a[mt][2], a[mt][3],
                             bfr[0], bfr[1]);
                    mma_tf32(acc[mt][np * 2 + 1], a[mt][0], a[mt][1], a[mt][2], a[mt][3],
                             bfr[2], bfr[3]);
                }
            }
        }
        mbar_arrive(MBE + s * 8);
    }

    /* epilogue */
    const int grp = lane >> 2;
    const int qid = lane & 3;
#pragma unroll
    for (int mt = 0; mt < 4; mt++) {
#pragma unroll
        for (int nt = 0; nt < 4; nt++) {
            const float* c = acc[mt][nt];
            int row = m0 + wm * 64 + mt * 16 + grp;
            int col = j0 + wn * 32 + nt * 8 + qid * 2;
#pragma unroll
            for (int half = 0; half < 2; half++) {
                int m = row + half * 8;
                float vx = c[half * 2], vy = c[half * 2 + 1];
                if (MODE == 0) {
                    int s  = col >> 10;
                    int rr = col & 1023;
                    int h  = rr >> 6;
                    int dh = rr & 63;
                    int b  = m >> 11;
                    int n  = m & 2047;
                    size_t idx = (((size_t)(b * H_ + h) * N_ + n) * DH_ + dh);
                    float sc = (s == 0) ? SCALE_ : 1.f;
                    uint32_t hi, lo;
                    split2(vx * sc, vy * sc, hi, lo);
                    __nv_bfloat16* bhp = (s == 0) ? g_qh : (s == 1) ? g_kh : g_vh;
                    __nv_bfloat16* blp = (s == 0) ? g_ql : (s == 1) ? g_kl : g_vl;
                    *reinterpret_cast<uint32_t*>(bhp + idx) = hi;
                    *reinterpret_cast<uint32_t*>(blp + idx) = lo;
                } else {
                    *reinterpret_cast<float2*>(C + (size_t)m * Nout + col) =
                        make_float2(vx, vy);
                }
            }
        }
    }
}

/* ------------------------------------------------------------------ */
/* Flash-attention (bf16 hi/lo). 2-stage KV pipeline on mbarriers.     */
/* V fragments via ldmatrix.trans. 2 CTAs/SM. Epilogue: tf32 ao.       */
/* (unchanged from R13)                                                */
/* ------------------------------------------------------------------ */
#define ASTR 72
#define QOFF 64
#define SM_QH 0
#define SM_QL (128 * ASTR)
#define SM_ST0 (2 * 128 * ASTR)
#define STG_E  (4 * 64 * ASTR)
#define OFF_KH 0
#define OFF_KL (64 * ASTR)
#define OFF_VH (2 * 64 * ASTR)
#define OFF_VL (3 * 64 * ASTR)
#define ATT_SMEM_BYTES (128 + (SM_ST0 + 2 * STG_E) * 2)   /* 110720 B */

__global__ void __launch_bounds__(256, 2)
attn_mma()
{
    extern __shared__ __nv_bfloat16 sbuf_raw[];
    __nv_bfloat16* sbuf = sbuf_raw + QOFF;

    const uint32_t sb0 = smem_u32(sbuf_raw);
    const uint32_t MBF = sb0;
    const uint32_t MBE = sb0 + 16;
    const uint32_t sB  = sb0 + 128;

    const int qt = (N_ / 128 - 1) - (blockIdx.x >> 5);
    const int bh = blockIdx.x & 31;
    const int b  = bh >> 4;
    const int h  = bh & 15;

    const int tid  = threadIdx.x;
    const int lane = tid & 31;
    const int w    = tid >> 5;

    const __nv_bfloat16* Qbh = g_qh + (size_t)bh * N_ * DH_;
    const __nv_bfloat16* Qbl = g_ql + (size_t)bh * N_ * DH_;
    const __nv_bfloat16* Kbh = g_kh + (size_t)bh * N_ * DH_;
    const __nv_bfloat16* Kbl = g_kl + (size_t)bh * N_ * DH_;
    const __nv_bfloat16* Vbh = g_vh + (size_t)bh * N_ * DH_;
    const __nv_bfloat16* Vbl = g_vl + (size_t)bh * N_ * DH_;

    if (tid == 0) {
#pragma unroll
        for (int s = 0; s < 2; s++) {
            mbar_init(MBF + s * 8, 256);
            mbar_init(MBE + s * 8, 256);
        }
    }
    __syncthreads();

    const int kr0 = tid >> 3;
    const int kr1 = (tid + 256) >> 3;
    const int kc8 = (tid & 7) * 8;
    const uint32_t kso0 = (uint32_t)(kr0 * ASTR + kc8) * 2;
    const uint32_t kso1 = (uint32_t)(kr1 * ASTR + kc8) * 2;

#define ISSUE_KV(jt, stage)                                                   \
    do {                                                                      \
        const size_t g0 = (size_t)((jt) * 64 + kr0) * DH_ + kc8;             \
        const size_t g1 = (size_t)((jt) * 64 + kr1) * DH_ + kc8;             \
        const uint32_t st_ = sB + (SM_ST0 + (stage) * STG_E) * 2;            \
        cp16(st_ + OFF_KH * 2 + kso0, Kbh + g0);                             \
        cp16(st_ + OFF_KH * 2 + kso1, Kbh + g1);                             \
        cp16(st_ + OFF_KL * 2 + kso0, Kbl + g0);                             \
        cp16(st_ + OFF_KL * 2 + kso1, Kbl + g1);                             \
        cp16(st_ + OFF_VH * 2 + kso0, Vbh + g0);                             \
        cp16(st_ + OFF_VH * 2 + kso1, Vbh + g1);                             \
        cp16(st_ + OFF_VL * 2 + kso0, Vbl + g0);                             \
        cp16(st_ + OFF_VL * 2 + kso1, Vbl + g1);                             \
        cp_arrive(MBF + (stage) * 8);                                        \
    } while (0)

    ISSUE_KV(0, 0);

#pragma unroll
    for (int it = 0; it < 4; it++) {
        int idx = tid + it * 256;
        int r   = idx >> 3;
        int c8  = (idx & 7) * 8;
        size_t g = (size_t)(qt * 128 + r) * DH_ + c8;
        *reinterpret_cast<uint4*>(sbuf + SM_QH + r * ASTR + c8) =
            *reinterpret_cast<const uint4*>(Qbh + g);
        *reinterpret_cast<uint4*>(sbuf + SM_QL + r * ASTR + c8) =
            *reinterpret_cast<const uint4*>(Qbl + g);
    }
    __syncthreads();

    uint32_t qh[4][4], ql[4][4];
    {
        const uint32_t a0 = sB +
            2u * ((uint32_t)((w * 16 + (lane & 15)) * ASTR) + ((lane >> 4) << 3));
#pragma unroll
        for (int ks = 0; ks < 4; ks++) {
            ldsm4(a0 + SM_QH * 2 + 2u * (ks * 16),
                  qh[ks][0], qh[ks][1], qh[ks][2], qh[ks][3]);
            ldsm4(a0 + SM_QL * 2 + 2u * (ks * 16),
                  ql[ks][0], ql[ks][1], ql[ks][2], ql[ks][3]);
        }
    }

    const uint32_t bpat = 2u * ((uint32_t)(((lane & 7) | ((lane & 16) >> 1)) * ASTR)
                                + (lane & 8));
    const uint32_t vpat = 2u * ((uint32_t)((lane & 15) * ASTR) + ((lane & 16) >> 1));

    float o[8][4];
#pragma unroll
    for (int i = 0; i < 8; i++)
#pragma unroll
        for (int c = 0; c < 4; c++) o[i][c] = 0.f;
    float mrow0 = -INFINITY, mrow1 = -INFINITY;
    float lrow0 = 0.f, lrow1 = 0.f;

    const int qglo   = qt * 128 + w * 16;
    const int ntiles = 2 * qt + 2;

    for (int jt = 0; jt < ntiles; jt++) {
        const int s = jt & 1;
        if (jt + 1 < ntiles) {
            const int s2 = (jt + 1) & 1;
            if (jt >= 1) mbar_wait(MBE + s2 * 8, (uint32_t)(((jt - 1) >> 1) & 1));
            ISSUE_KV(jt + 1, s2);
        }

        mbar_wait(MBF + s * 8, (uint32_t)((jt >> 1) & 1));

        if (jt * 64 <= qglo + 15) {
            const uint32_t stg = sB + (SM_ST0 + s * STG_E) * 2;
            const uint32_t sKH = stg + OFF_KH * 2;
            const uint32_t sKL = stg + OFF_KL * 2;
            const uint32_t sVH = stg + OFF_VH * 2;
            const uint32_t sVL = stg + OFF_VL * 2;

            float sfr[8][4];
#pragma unroll
            for (int i = 0; i < 8; i++)
#pragma unroll
                for (int c = 0; c < 4; c++) sfr[i][c] = 0.f;

#pragma unroll
            for (int ks = 0; ks < 4; ks++) {
#pragma unroll
                for (int np = 0; np < 4; np++) {
                    const uint32_t boff = bpat + 2u * (np * 16 * ASTR + ks * 16);
                    uint32_t bh4[4], bl4[4];
                    ldsm4(sKH + boff, bh4[0], bh4[1], bh4[2], bh4[3]);
                    ldsm4(sKL + boff, bl4[0], bl4[1], bl4[2], bl4[3]);
#pragma unroll
                    for (int sub = 0; sub < 2; sub++) {
                        float* c = sfr[np * 2 + sub];
                        mma16816(c, qh[ks][0], qh[ks][1], qh[ks][2], qh[ks][3],
                                 bh4[sub * 2], bh4[sub * 2 + 1]);
                        mma16816(c, qh[ks][0], qh[ks][1], qh[ks][2], qh[ks][3],
                                 bl4[sub * 2], bl4[sub * 2 + 1]);
                        mma16816(c, ql[ks][0], ql[ks][1], ql[ks][2], ql[ks][3],
                                 bh4[sub * 2], bh4[sub * 2 + 1]);
                    }
                }
            }

            const int r0 = qglo + (lane >> 2);
            const int r1 = r0 + 8;
            if (jt * 64 + 63 > qglo) {
                const int colb = jt * 64 + (lane & 3) * 2;
#pragma unroll
                for (int nt = 0; nt < 8; nt++) {
                    int c0 = colb + nt * 8;
                    if (c0 > r0)     sfr[nt][0] = -INFINITY;
                    if (c0 + 1 > r0) sfr[nt][1] = -INFINITY;
                    if (c0 > r1)     sfr[nt][2] = -INFINITY;
                    if (c0 + 1 > r1) sfr[nt][3] = -INFINITY;
                }
            }

            float mt0 = sfr[0][0], mt1 = sfr[0][2];
#pragma unroll
            for (int nt = 0; nt < 8; nt++) {
                mt0 = fmaxf(mt0, fmaxf(sfr[nt][0], sfr[nt][1]));
                mt1 = fmaxf(mt1, fmaxf(sfr[nt][2], sfr[nt][3]));
            }
            mt0 = fmaxf(mt0, __shfl_xor_sync(0xffffffffu, mt0, 1));
            mt0 = fmaxf(mt0, __shfl_xor_sync(0xffffffffu, mt0, 2));
            mt1 = fmaxf(mt1, __shfl_xor_sync(0xffffffffu, mt1, 1));
            mt1 = fmaxf(mt1, __shfl_xor_sync(0xffffffffu, mt1, 2));

            const float mn0 = fmaxf(mrow0, mt0);
            const float mn1 = fmaxf(mrow1, mt1);
            const float al0 = __expf(mrow0 - mn0);
            const float al1 = __expf(mrow1 - mn1);

            float ps0 = 0.f, ps1 = 0.f;
#pragma unroll
            for (int nt = 0; nt < 8; nt++) {
                sfr[nt][0] = __expf(sfr[nt][0] - mn0);
                sfr[nt][1] = __expf(sfr[nt][1] - mn0);
                sfr[nt][2] = __expf(sfr[nt][2] - mn1);
                sfr[nt][3] = __expf(sfr[nt][3] - mn1);
                ps0 += sfr[nt][0] + sfr[nt][1];
                ps1 += sfr[nt][2] + sfr[nt][3];
            }
            ps0 += __shfl_xor_sync(0xffffffffu, ps0, 1);
            ps0 += __shfl_xor_sync(0xffffffffu, ps0, 2);
            ps1 += __shfl_xor_sync(0xffffffffu, ps1, 1);
            ps1 += __shfl_xor_sync(0xffffffffu, ps1, 2);

            lrow0 = lrow0 * al0 + ps0;
            lrow1 = lrow1 * al1 + ps1;
#pragma unroll
            for (int nt = 0; nt < 8; nt++) {
                o[nt][0] *= al0; o[nt][1] *= al0;
                o[nt][2] *= al1; o[nt][3] *= al1;
            }
            mrow0 = mn0;
            mrow1 = mn1;

#pragma unroll
            for (int ks = 0; ks < 4; ks++) {
                uint32_t ph[4], pl[4];
                split2(sfr[2 * ks][0],     sfr[2 * ks][1],     ph[0], pl[0]);
                split2(sfr[2 * ks][2],     sfr[2 * ks][3],     ph[1], pl[1]);
                split2(sfr[2 * ks + 1][0], sfr[2 * ks + 1][1], ph[2], pl[2]);
                split2(sfr[2 * ks + 1][2], sfr[2 * ks + 1][3], ph[3], pl[3]);
#pragma unroll
                for (int np = 0; np < 4; np++) {
                    const uint32_t voff = vpat + 2u * (ks * 16 * ASTR + np * 16);
                    uint32_t bh4[4], bl4[4];
                    ldsm4t(sVH + voff, bh4[0], bh4[1], bh4[2], bh4[3]);
                    ldsm4t(sVL + voff, bl4[0], bl4[1], bl4[2], bl4[3]);
#pragma unroll
                    for (int sub = 0; sub < 2; sub++) {
                        float* c = o[np * 2 + sub];
                        mma16816(c, ph[0], ph[1], ph[2], ph[3],
                                 bh4[sub * 2], bh4[sub * 2 + 1]);
                        mma16816(c, ph[0], ph[1], ph[2], ph[3],
                                 bl4[sub * 2], bl4[sub * 2 + 1]);
                        mma16816(c, pl[0], pl[1], pl[2], pl[3],
                                 bh4[sub * 2], bh4[sub * 2 + 1]);
                    }
                }
            }
        }

        mbar_arrive(MBE + s * 8);
    }

    /* ---- epilogue: normalize, write tf32-rounded ao ---- */
    const float i0 = 1.f / lrow0;
    const float i1 = 1.f / lrow1;
    const int r0 = qt * 128 + w * 16 + (lane >> 2);
    const size_t base0 = ((size_t)b * N_ + r0) * D_ + h * DH_ + (lane & 3) * 2;
    const size_t base1 = base0 + 8 * D_;
#pragma unroll
    for (int nt = 0; nt < 8; nt++) {
        float2 v0 = make_float2(o[nt][0] * i0, o[nt][1] * i0);
        float2 v1 = make_float2(o[nt][2] * i1, o[nt][3] * i1);
        asm("cvt.rna.tf32.f32 %0, %1;" : "=r"(*(uint32_t*)&v0.x) : "f"(v0.x));
        asm("cvt.rna.tf32.f32 %0, %1;" : "=r"(*(uint32_t*)&v0.y) : "f"(v0.y));
        asm("cvt.rna.tf32.f32 %0, %1;" : "=r"(*(uint32_t*)&v1.x) : "f"(v1.x));
        asm("cvt.rna.tf32.f32 %0, %1;" : "=r"(*(uint32_t*)&v1.y) : "f"(v1.y));
        *reinterpret_cast<float2*>(g_aor + base0 + nt * 8) = v0;
        *reinterpret_cast<float2*>(g_aor + base1 + nt * 8) = v1;
    }
}

/* ------------------------------------------------------------------ */
extern "C" void kernel_launch(void* const* d_in, const int* in_sizes, int n_in,
                              void* d_out, int out_size)
{
    const float* x    = (const float*)d_in[0];
    /* d_in[1] = mask (static causal structure, unused) */
    const float* Wqkv = (const float*)d_in[2];
    const float* Wout = (const float*)d_in[3];
    float* out = (float*)d_out;

    float *xr, *wqr, *wor, *aor;
    cudaGetSymbolAddress((void**)&xr,  g_xr);
    cudaGetSymbolAddress((void**)&wqr, g_wqr);
    cudaGetSymbolAddress((void**)&wor, g_wor);
    cudaGetSymbolAddress((void**)&aor, g_aor);

    /* 0. pre-round inputs to tf32 (rna) */
    round_tf32<<<1024, 256>>>(x,    xr,  4096 * 1024 / 4);
    round_tf32<<<1024, 256>>>(Wqkv, wqr, 3072 * 1024 / 4);
    round_tf32<<<512,  256>>>(Wout, wor, 1024 * 1024 / 4);

    cudaFuncSetAttribute(gemm_tf32<0>,
                         cudaFuncAttributeMaxDynamicSharedMemorySize, GEMM_SMEM);
    cudaFuncSetAttribute(gemm_tf32<1>,
                         cudaFuncAttributeMaxDynamicSharedMemorySize, GEMM_SMEM);

    /* 1. QKV projection (tf32) -> q/k/v bf16 hi/lo (q pre-scaled) */
    gemm_tf32<0><<<dim3(3072 / 128, 4096 / 256), 512, GEMM_SMEM>>>(
        xr, wqr, nullptr, D_, 3 * D_);

    /* 2. causal flash attention (bf16 hi/lo) -> tf32-rounded ao */
    cudaFuncSetAttribute(attn_mma,
                         cudaFuncAttributeMaxDynamicSharedMemorySize, ATT_SMEM_BYTES);
    attn_mma<<<dim3((N_ / 128) * 32), 256, ATT_SMEM_BYTES>>>();

    /* 3. output projection (tf32) -> d_out (fp32) */
    gemm_tf32<1><<<dim3(1024 / 128, 4096 / 256), 512, GEMM_SMEM>>>(
        aor, wor, out, D_, D_);
}

// round 15
// speedup vs baseline: 1.0795x; 1.0042x over previous
#include <cuda_runtime.h>
#include <cuda_bf16.h>
#include <math.h>
#include <stdint.h>

#define B_ 2
#define N_ 2048
#define D_ 1024
#define H_ 16
#define DH_ 64
#define SCALE_ 0.125f   /* 64^-0.5, exact power of two */

/* ------------------------------------------------------------------ */
/* device scratch                                                      */
/* ------------------------------------------------------------------ */
__device__ float g_xr [4096 * 1024];   /* tf32-rounded x      */
__device__ float g_wqr[3072 * 1024];   /* tf32-rounded W_qkv  */
__device__ float g_wor[1024 * 1024];   /* tf32-rounded W_out  */
__device__ __nv_bfloat16 g_qh[B_*H_*N_*DH_], g_ql[B_*H_*N_*DH_];
__device__ __nv_bfloat16 g_kh[B_*H_*N_*DH_], g_kl[B_*H_*N_*DH_];
__device__ __nv_bfloat16 g_vh[B_*H_*N_*DH_], g_vl[B_*H_*N_*DH_];
__device__ float         g_aor[B_*N_*D_];  /* tf32-rounded ao */

/* ------------------------------------------------------------------ */
/* helpers                                                             */
/* ------------------------------------------------------------------ */
__device__ __forceinline__ uint32_t smem_u32(const void* p) {
    uint32_t a;
    asm("{ .reg .u64 t; cvta.to.shared.u64 t, %1; cvt.u32.u64 %0, t; }"
        : "=r"(a) : "l"(p));
    return a;
}

/* swizzle for 128B-row fp32 tiles: chunk' = chunk ^ (row & 7) */
__device__ __forceinline__ uint32_t swzA(uint32_t o) {
    return o ^ (((o >> 7) & 7u) << 4);
}

__device__ __forceinline__ void ldsm4(uint32_t addr, uint32_t& r0, uint32_t& r1,
                                      uint32_t& r2, uint32_t& r3) {
    asm volatile("ldmatrix.sync.aligned.m8n8.x4.shared.b16 {%0,%1,%2,%3}, [%4];"
                 : "=r"(r0), "=r"(r1), "=r"(r2), "=r"(r3) : "r"(addr));
}

__device__ __forceinline__ void ldsm4t(uint32_t addr, uint32_t& r0, uint32_t& r1,
                                       uint32_t& r2, uint32_t& r3) {
    asm volatile("ldmatrix.sync.aligned.m8n8.x4.trans.shared.b16 {%0,%1,%2,%3}, [%4];"
                 : "=r"(r0), "=r"(r1), "=r"(r2), "=r"(r3) : "r"(addr));
}

__device__ __forceinline__ void mma16816(float* c,
                                         uint32_t a0, uint32_t a1, uint32_t a2, uint32_t a3,
                                         uint32_t b0, uint32_t b1) {
    asm volatile(
        "mma.sync.aligned.m16n8k16.row.col.f32.bf16.bf16.f32 "
        "{%0,%1,%2,%3}, {%4,%5,%6,%7}, {%8,%9}, {%0,%1,%2,%3};"
        : "+f"(c[0]), "+f"(c[1]), "+f"(c[2]), "+f"(c[3])
        : "r"(a0), "r"(a1), "r"(a2), "r"(a3), "r"(b0), "r"(b1));
}

__device__ __forceinline__ void mma_tf32(float* c,
                                         uint32_t a0, uint32_t a1, uint32_t a2, uint32_t a3,
                                         uint32_t b0, uint32_t b1) {
    asm volatile(
        "mma.sync.aligned.m16n8k8.row.col.f32.tf32.tf32.f32 "
        "{%0,%1,%2,%3}, {%4,%5,%6,%7}, {%8,%9}, {%0,%1,%2,%3};"
        : "+f"(c[0]), "+f"(c[1]), "+f"(c[2]), "+f"(c[3])
        : "r"(a0), "r"(a1), "r"(a2), "r"(a3), "r"(b0), "r"(b1));
}

__device__ __forceinline__ void split2(float x, float y, uint32_t& hi, uint32_t& lo) {
    __nv_bfloat162 h = __floats2bfloat162_rn(x, y);
    float rx = x - __bfloat162float(h.x);
    float ry = y - __bfloat162float(h.y);
    __nv_bfloat162 l = __floats2bfloat162_rn(rx, ry);
    hi = *reinterpret_cast<uint32_t*>(&h);
    lo = *reinterpret_cast<uint32_t*>(&l);
}

__device__ __forceinline__ void cp16(uint32_t saddr, const void* g) {
    asm volatile("cp.async.cg.shared.global [%0], [%1], 16;"
                 :: "r"(saddr), "l"(g) : "memory");
}

/* ---- mbarrier primitives (sm_90 generic) ---- */
__device__ __forceinline__ void mbar_init(uint32_t a, uint32_t cnt) {
    asm volatile("mbarrier.init.shared.b64 [%0], %1;" :: "r"(a), "r"(cnt) : "memory");
}
__device__ __forceinline__ void mbar_arrive(uint32_t a) {
    asm volatile("mbarrier.arrive.shared.b64 _, [%0];" :: "r"(a) : "memory");
}
__device__ __forceinline__ void cp_arrive(uint32_t a) {
    asm volatile("cp.async.mbarrier.arrive.noinc.shared.b64 [%0];"
                 :: "r"(a) : "memory");
}
__device__ __forceinline__ void mbar_wait(uint32_t a, uint32_t parity) {
    asm volatile(
        "{\n\t.reg .pred P;\n"
        "W_%=:\n\t"
        "mbarrier.try_wait.parity.acquire.cta.shared::cta.b64 P, [%0], %1;\n\t"
        "@P bra D_%=;\n\t"
        "bra W_%=;\n"
        "D_%=:\n\t}"
        :: "r"(a), "r"(parity) : "memory");
}

/* ------------------------------------------------------------------ */
/* round kernel: fp32 -> tf32-rounded fp32 (rna)                       */
/* ------------------------------------------------------------------ */
__global__ void __launch_bounds__(256)
round_tf32(const float* __restrict__ src, float* __restrict__ dst, int n4)
{
    int i      = blockIdx.x * blockDim.x + threadIdx.x;
    int stride = gridDim.x * blockDim.x;
    for (; i < n4; i += stride) {
        float4 v = reinterpret_cast<const float4*>(src)[i];
        float4 r;
        asm("cvt.rna.tf32.f32 %0, %1;" : "=r"(*(uint32_t*)&r.x) : "f"(v.x));
        asm("cvt.rna.tf32.f32 %0, %1;" : "=r"(*(uint32_t*)&r.y) : "f"(v.y));
        asm("cvt.rna.tf32.f32 %0, %1;" : "=r"(*(uint32_t*)&r.z) : "f"(v.z));
        asm("cvt.rna.tf32.f32 %0, %1;" : "=r"(*(uint32_t*)&r.w) : "f"(v.w));
        reinterpret_cast<float4*>(dst)[i] = r;
    }
}

/* ------------------------------------------------------------------ */
/* TF32 HMMA GEMM on pre-rounded fp32: C = A * W^T.                    */
/* CTA tile 256x128, BK=32, 512 thr (16 warps 4x4), warp tile 64x32.   */
/* 4-stage mbarrier full/empty pipeline (prefetch distance 3).         */
/* MODE 0: epilogue -> q/k/v bf16 hi/lo (q scaled). MODE 1: fp32 C.    */
/* ------------------------------------------------------------------ */
#define GARR_A (256 * 128u)                 /* A stage bytes (32 KB)  */
#define GARR_W (128 * 128u)                 /* W stage bytes (16 KB)  */
#define GSTAGE_B (GARR_A + GARR_W)          /* 48 KB per stage        */
#define GSTAGES 4
#define GEMM_SMEM (128 + GSTAGES * GSTAGE_B)  /* 196736 B dynamic     */

template <int MODE>
__global__ void __launch_bounds__(512, 1)
gemm_tf32(const float* __restrict__ A, const float* __restrict__ W,
          float* __restrict__ C, int K, int Nout)
{
    extern __shared__ float smem[];
    const uint32_t sb = smem_u32(smem);
    /* mbarriers: full[4] at sb+0..24 ; empty[4] at sb+32..56 */
    const uint32_t MBF = sb;
    const uint32_t MBE = sb + 32;
    const uint32_t DB  = sb + 128;          /* data base */

    const int tid  = threadIdx.x;
    const int lane = tid & 31;
    const int wid  = tid >> 5;        /* 0..15 */
    const int wm   = wid & 3;         /* 64-row slice   */
    const int wn   = wid >> 2;        /* 32-col slice   */

    const int m0 = blockIdx.y * 256;
    const int j0 = blockIdx.x * 128;

    if (tid == 0) {
#pragma unroll
        for (int s = 0; s < GSTAGES; s++) {
            mbar_init(MBF + s * 8, 512);
            mbar_init(MBE + s * 8, 512);
        }
    }
    __syncthreads();

    const int q0 = tid & 7;

#define ISSUE_CHUNK(kc, stage)                                                \
    do {                                                                      \
        const int koff = (kc) * 32;                                          \
        const uint32_t st_ = DB + (uint32_t)(stage) * GSTAGE_B;              \
        _Pragma("unroll")                                                     \
        for (int i_ = 0; i_ < 4; i_++) {                                     \
            int r_ = (tid + i_ * 512) >> 3;                                  \
            uint32_t so_ = swzA((uint32_t)(r_ * 128 + q0 * 16));             \
            cp16(st_ + so_, A + (size_t)(m0 + r_) * K + koff + q0 * 4);      \
        }                                                                     \
        _Pragma("unroll")                                                     \
        for (int i_ = 0; i_ < 2; i_++) {                                     \
            int r_ = (tid + i_ * 512) >> 3;                                  \
            uint32_t so_ = swzA((uint32_t)(r_ * 128 + q0 * 16));             \
            cp16(st_ + GARR_A + so_, W + (size_t)(j0 + r_) * K + koff + q0 * 4); \
        }                                                                     \
        cp_arrive(MBF + (stage) * 8);                                        \
    } while (0)

    /* ldsm lane address components */
    const int a_r8 = lane & 7;
    const int a_rh = (lane >> 3) & 1;
    const int a_ch = lane >> 4;
    const int b_rh = lane >> 4;
    const int b_ch = (lane >> 3) & 1;

    float acc[4][4][4];
#pragma unroll
    for (int i = 0; i < 4; i++)
#pragma unroll
        for (int j = 0; j < 4; j++)
#pragma unroll
            for (int c = 0; c < 4; c++) acc[i][j][c] = 0.f;

    const int nchunk = K >> 5;   /* 32 */

    ISSUE_CHUNK(0, 0);
    ISSUE_CHUNK(1, 1);
    ISSUE_CHUNK(2, 2);

    for (int kc = 0; kc < nchunk; kc++) {
        const int s = kc & 3;                     /* kc % 4 */
        if (kc + 3 < nchunk) {
            const int s2 = (kc + 3) & 3;          /* == (kc-1)&3 */
            if (kc >= 1) mbar_wait(MBE + s2 * 8, (uint32_t)(((kc - 1) >> 2) & 1));
            ISSUE_CHUNK(kc + 3, s2);
        }

        mbar_wait(MBF + s * 8, (uint32_t)((kc >> 2) & 1));

        const uint32_t stg = DB + (uint32_t)s * GSTAGE_B;
        const uint32_t sA  = stg;
        const uint32_t sW  = stg + GARR_A;

#pragma unroll
        for (int ks = 0; ks < 4; ks++) {       /* k8 steps within BK=32 */
            uint32_t a[4][4];
#pragma unroll
            for (int mt = 0; mt < 4; mt++) {
                int row   = wm * 64 + mt * 16 + a_r8 + a_rh * 8;
                int chunk = ks * 2 + a_ch;
                uint32_t addr = sA + swzA((uint32_t)(row * 128 + chunk * 16));
                ldsm4(addr, a[mt][0], a[mt][1], a[mt][2], a[mt][3]);
            }
#pragma unroll
            for (int np = 0; np < 2; np++) {
                int row   = wn * 32 + np * 16 + a_r8 + b_rh * 8;
                int chunk = ks * 2 + b_ch;
                uint32_t addr = sW + swzA((uint32_t)(row * 128 + chunk * 16));
                uint32_t bfr[4];
                ldsm4(addr, bfr[0], bfr[1], bfr[2], bfr[3]);
#pragma unroll
                for (int mt = 0; mt < 4; mt++) {
                    mma_tf32(acc[mt][np * 2 + 0], a[mt][0], a[mt][1], a[mt][2], a[mt][3],
                             bfr[0], bfr[1]);
                    mma_tf32(acc[mt][np * 2 + 1], a[mt][0], a[mt][1], a[mt][2], a[mt][3],
                             bfr[2], bfr[3]);
                }
            }
        }
        mbar_arrive(MBE + s * 8);
    }

    /* epilogue */
    const int grp = lane >> 2;
    const int qid = lane & 3;
#pragma unroll
    for (int mt = 0; mt < 4; mt++) {
#pragma unroll
        for (int nt = 0; nt < 4; nt++) {
            const float* c = acc[mt][nt];
            int row = m0 + wm * 64 + mt * 16 + grp;
            int col = j0 + wn * 32 + nt * 8 + qid * 2;
#pragma unroll
            for (int half = 0; half < 2; half++) {
                int m = row + half * 8;
                float vx = c[half * 2], vy = c[half * 2 + 1];
                if (MODE == 0) {
                    int s  = col >> 10;
                    int rr = col & 1023;
                    int h  = rr >> 6;
                    int dh = rr & 63;
                    int b  = m >> 11;
                    int n  = m & 2047;
                    size_t idx = (((size_t)(b * H_ + h) * N_ + n) * DH_ + dh);
                    float sc = (s == 0) ? SCALE_ : 1.f;
                    uint32_t hi, lo;
                    split2(vx * sc, vy * sc, hi, lo);
                    __nv_bfloat16* bhp = (s == 0) ? g_qh : (s == 1) ? g_kh : g_vh;
                    __nv_bfloat16* blp = (s == 0) ? g_ql : (s == 1) ? g_kl : g_vl;
                    *reinterpret_cast<uint32_t*>(bhp + idx) = hi;
                    *reinterpret_cast<uint32_t*>(blp + idx) = lo;
                } else {
                    *reinterpret_cast<float2*>(C + (size_t)m * Nout + col) =
                        make_float2(vx, vy);
                }
            }
        }
    }
}

/* ------------------------------------------------------------------ */
/* Flash-attention (bf16 hi/lo). 2-stage KV pipeline on mbarriers;     */
/* skip-warps bypass the full-wait. V via ldmatrix.trans. 2 CTAs/SM.   */
/* ------------------------------------------------------------------ */
#define ASTR 72
#define QOFF 64
#define SM_QH 0
#define SM_QL (128 * ASTR)
#define SM_ST0 (2 * 128 * ASTR)
#define STG_E  (4 * 64 * ASTR)
#define OFF_KH 0
#define OFF_KL (64 * ASTR)
#define OFF_VH (2 * 64 * ASTR)
#define OFF_VL (3 * 64 * ASTR)
#define ATT_SMEM_BYTES (128 + (SM_ST0 + 2 * STG_E) * 2)   /* 110720 B */

__global__ void __launch_bounds__(256, 2)
attn_mma()
{
    extern __shared__ __nv_bfloat16 sbuf_raw[];
    __nv_bfloat16* sbuf = sbuf_raw + QOFF;

    const uint32_t sb0 = smem_u32(sbuf_raw);
    const uint32_t MBF = sb0;
    const uint32_t MBE = sb0 + 16;
    const uint32_t sB  = sb0 + 128;

    const int qt = (N_ / 128 - 1) - (blockIdx.x >> 5);
    const int bh = blockIdx.x & 31;
    const int b  = bh >> 4;
    const int h  = bh & 15;

    const int tid  = threadIdx.x;
    const int lane = tid & 31;
    const int w    = tid >> 5;

    const __nv_bfloat16* Qbh = g_qh + (size_t)bh * N_ * DH_;
    const __nv_bfloat16* Qbl = g_ql + (size_t)bh * N_ * DH_;
    const __nv_bfloat16* Kbh = g_kh + (size_t)bh * N_ * DH_;
    const __nv_bfloat16* Kbl = g_kl + (size_t)bh * N_ * DH_;
    const __nv_bfloat16* Vbh = g_vh + (size_t)bh * N_ * DH_;
    const __nv_bfloat16* Vbl = g_vl + (size_t)bh * N_ * DH_;

    if (tid == 0) {
#pragma unroll
        for (int s = 0; s < 2; s++) {
            mbar_init(MBF + s * 8, 256);
            mbar_init(MBE + s * 8, 256);
        }
    }
    __syncthreads();

    const int kr0 = tid >> 3;
    const int kr1 = (tid + 256) >> 3;
    const int kc8 = (tid & 7) * 8;
    const uint32_t kso0 = (uint32_t)(kr0 * ASTR + kc8) * 2;
    const uint32_t kso1 = (uint32_t)(kr1 * ASTR + kc8) * 2;

#define ISSUE_KV(jt, stage)                                                   \
    do {                                                                      \
        const size_t g0 = (size_t)((jt) * 64 + kr0) * DH_ + kc8;             \
        const size_t g1 = (size_t)((jt) * 64 + kr1) * DH_ + kc8;             \
        const uint32_t st_ = sB + (SM_ST0 + (stage) * STG_E) * 2;            \
        cp16(st_ + OFF_KH * 2 + kso0, Kbh + g0);                             \
        cp16(st_ + OFF_KH * 2 + kso1, Kbh + g1);                             \
        cp16(st_ + OFF_KL * 2 + kso0, Kbl + g0);                             \
        cp16(st_ + OFF_KL * 2 + kso1, Kbl + g1);                             \
        cp16(st_ + OFF_VH * 2 + kso0, Vbh + g0);                             \
        cp16(st_ + OFF_VH * 2 + kso1, Vbh + g1);                             \
        cp16(st_ + OFF_VL * 2 + kso0, Vbl + g0);                             \
        cp16(st_ + OFF_VL * 2 + kso1, Vbl + g1);                             \
        cp_arrive(MBF + (stage) * 8);                                        \
    } while (0)

    ISSUE_KV(0, 0);

#pragma unroll
    for (int it = 0; it < 4; it++) {
        int idx = tid + it * 256;
        int r   = idx >> 3;
        int c8  = (idx & 7) * 8;
        size_t g = (size_t)(qt * 128 + r) * DH_ + c8;
        *reinterpret_cast<uint4*>(sbuf + SM_QH + r * ASTR + c8) =
            *reinterpret_cast<const uint4*>(Qbh + g);
        *reinterpret_cast<uint4*>(sbuf + SM_QL + r * ASTR + c8) =
            *reinterpret_cast<const uint4*>(Qbl + g);
    }
    __syncthreads();

    uint32_t qh[4][4], ql[4][4];
    {
        const uint32_t a0 = sB +
            2u * ((uint32_t)((w * 16 + (lane & 15)) * ASTR) + ((lane >> 4) << 3));
#pragma unroll
        for (int ks = 0; ks < 4; ks++) {
            ldsm4(a0 + SM_QH * 2 + 2u * (ks * 16),
                  qh[ks][0], qh[ks][1], qh[ks][2], qh[ks][3]);
            ldsm4(a0 + SM_QL * 2 + 2u * (ks * 16),
                  ql[ks][0], ql[ks][1], ql[ks][2], ql[ks][3]);
        }
    }

    const uint32_t bpat = 2u * ((uint32_t)(((lane & 7) | ((lane & 16) >> 1)) * ASTR)
                                + (lane & 8));
    const uint32_t vpat = 2u * ((uint32_t)((lane & 15) * ASTR) + ((lane & 16) >> 1));

    float o[8][4];
#pragma unroll
    for (int i = 0; i < 8; i++)
#pragma unroll
        for (int c = 0; c < 4; c++) o[i][c] = 0.f;
    float mrow0 = -INFINITY, mrow1 = -INFINITY;
    float lrow0 = 0.f, lrow1 = 0.f;

    const int qglo   = qt * 128 + w * 16;
    const int ntiles = 2 * qt + 2;

    for (int jt = 0; jt < ntiles; jt++) {
        const int s = jt & 1;
        if (jt + 1 < ntiles) {
            const int s2 = (jt + 1) & 1;
            if (jt >= 1) mbar_wait(MBE + s2 * 8, (uint32_t)(((jt - 1) >> 1) & 1));
            ISSUE_KV(jt + 1, s2);
        }

        /* skip-warp fast path: declare stage consumed without waiting */
        if (jt * 64 > qglo + 15) {
            mbar_arrive(MBE + s * 8);
            continue;
        }

        mbar_wait(MBF + s * 8, (uint32_t)((jt >> 1) & 1));

        {
            const uint32_t stg = sB + (SM_ST0 + s * STG_E) * 2;
            const uint32_t sKH = stg + OFF_KH * 2;
            const uint32_t sKL = stg + OFF_KL * 2;
            const uint32_t sVH = stg + OFF_VH * 2;
            const uint32_t sVL = stg + OFF_VL * 2;

            float sfr[8][4];
#pragma unroll
            for (int i = 0; i < 8; i++)
#pragma unroll
                for (int c = 0; c < 4; c++) sfr[i][c] = 0.f;

#pragma unroll
            for (int ks = 0; ks < 4; ks++) {
#pragma unroll
                for (int np = 0; np < 4; np++) {
                    const uint32_t boff = bpat + 2u * (np * 16 * ASTR + ks * 16);
                    uint32_t bh4[4], bl4[4];
                    ldsm4(sKH + boff, bh4[0], bh4[1], bh4[2], bh4[3]);
                    ldsm4(sKL + boff, bl4[0], bl4[1], bl4[2], bl4[3]);
#pragma unroll
                    for (int sub = 0; sub < 2; sub++) {
                        float* c = sfr[np * 2 + sub];
                        mma16816(c, qh[ks][0], qh[ks][1], qh[ks][2], qh[ks][3],
                                 bh4[sub * 2], bh4[sub * 2 + 1]);
                        mma16816(c, qh[ks][0], qh[ks][1], qh[ks][2], qh[ks][3],
                                 bl4[sub * 2], bl4[sub * 2 + 1]);
                        mma16816(c, ql[ks][0], ql[ks][1], ql[ks][2], ql[ks][3],
                                 bh4[sub * 2], bh4[sub * 2 + 1]);
                    }
                }
            }

            const int r0 = qglo + (lane >> 2);
            const int r1 = r0 + 8;
            if (jt * 64 + 63 > qglo) {
                const int colb = jt * 64 + (lane & 3) * 2;
#pragma unroll
                for (int nt = 0; nt < 8; nt++) {
                    int c0 = colb + nt * 8;
                    if (c0 > r0)     sfr[nt][0] = -INFINITY;
                    if (c0 + 1 > r0) sfr[nt][1] = -INFINITY;
                    if (c0 > r1)     sfr[nt][2] = -INFINITY;
                    if (c0 + 1 > r1) sfr[nt][3] = -INFINITY;
                }
            }

            float mt0 = sfr[0][0], mt1 = sfr[0][2];
#pragma unroll
            for (int nt = 0; nt < 8; nt++) {
                mt0 = fmaxf(mt0, fmaxf(sfr[nt][0], sfr[nt][1]));
                mt1 = fmaxf(mt1, fmaxf(sfr[nt][2], sfr[nt][3]));
            }
            mt0 = fmaxf(mt0, __shfl_xor_sync(0xffffffffu, mt0, 1));
            mt0 = fmaxf(mt0, __shfl_xor_sync(0xffffffffu, mt0, 2));
            mt1 = fmaxf(mt1, __shfl_xor_sync(0xffffffffu, mt1, 1));
            mt1 = fmaxf(mt1, __shfl_xor_sync(0xffffffffu, mt1, 2));

            const float mn0 = fmaxf(mrow0, mt0);
            const float mn1 = fmaxf(mrow1, mt1);
            const float al0 = __expf(mrow0 - mn0);
            const float al1 = __expf(mrow1 - mn1);

            float ps0 = 0.f, ps1 = 0.f;
#pragma unroll
            for (int nt = 0; nt < 8; nt++) {
                sfr[nt][0] = __expf(sfr[nt][0] - mn0);
                sfr[nt][1] = __expf(sfr[nt][1] - mn0);
                sfr[nt][2] = __expf(sfr[nt][2] - mn1);
                sfr[nt][3] = __expf(sfr[nt][3] - mn1);
                ps0 += sfr[nt][0] + sfr[nt][1];
                ps1 += sfr[nt][2] + sfr[nt][3];
            }
            ps0 += __shfl_xor_sync(0xffffffffu, ps0, 1);
            ps0 += __shfl_xor_sync(0xffffffffu, ps0, 2);
            ps1 += __shfl_xor_sync(0xffffffffu, ps1, 1);
            ps1 += __shfl_xor_sync(0xffffffffu, ps1, 2);

            lrow0 = lrow0 * al0 + ps0;
            lrow1 = lrow1 * al1 + ps1;
#pragma unroll
            for (int nt = 0; nt < 8; nt++) {
                o[nt][0] *= al0; o[nt][1] *= al0;
                o[nt][2] *= al1; o[nt][3] *= al1;
            }
            mrow0 = mn0;
            mrow1 = mn1;

#pragma unroll
            for (int ks = 0; ks < 4; ks++) {
                uint32_t ph[4], pl[4];
                split2(sfr[2 * ks][0],     sfr[2 * ks][1],     ph[0], pl[0]);
                split2(sfr[2 * ks][2],     sfr[2 * ks][3],     ph[1], pl[1]);
                split2(sfr[2 * ks + 1][0], sfr[2 * ks + 1][1], ph[2], pl[2]);
                split2(sfr[2 * ks + 1][2], sfr[2 * ks + 1][3], ph[3], pl[3]);
#pragma unroll
                for (int np = 0; np < 4; np++) {
                    const uint32_t voff = vpat + 2u * (ks * 16 * ASTR + np * 16);
                    uint32_t bh4[4], bl4[4];
                    ldsm4t(sVH + voff, bh4[0], bh4[1], bh4[2], bh4[3]);
                    ldsm4t(sVL + voff, bl4[0], bl4[1], bl4[2], bl4[3]);
#pragma unroll
                    for (int sub = 0; sub < 2; sub++) {
                        float* c = o[np * 2 + sub];
                        mma16816(c, ph[0], ph[1], ph[2], ph[3],
                                 bh4[sub * 2], bh4[sub * 2 + 1]);
                        mma16816(c, ph[0], ph[1], ph[2], ph[3],
                                 bl4[sub * 2], bl4[sub * 2 + 1]);
                        mma16816(c, pl[0], pl[1], pl[2], pl[3],
                                 bh4[sub * 2], bh4[sub * 2 + 1]);
                    }
                }
            }
        }

        mbar_arrive(MBE + s * 8);
    }

    /* ---- epilogue: normalize, write tf32-rounded ao ---- */
    const float i0 = 1.f / lrow0;
    const float i1 = 1.f / lrow1;
    const int r0 = qt * 128 + w * 16 + (lane >> 2);
    const size_t base0 = ((size_t)b * N_ + r0) * D_ + h * DH_ + (lane & 3) * 2;
    const size_t base1 = base0 + 8 * D_;
#pragma unroll
    for (int nt = 0; nt < 8; nt++) {
        float2 v0 = make_float2(o[nt][0] * i0, o[nt][1] * i0);
        float2 v1 = make_float2(o[nt][2] * i1, o[nt][3] * i1);
        asm("cvt.rna.tf32.f32 %0, %1;" : "=r"(*(uint32_t*)&v0.x) : "f"(v0.x));
        asm("cvt.rna.tf32.f32 %0, %1;" : "=r"(*(uint32_t*)&v0.y) : "f"(v0.y));
        asm("cvt.rna.tf32.f32 %0, %1;" : "=r"(*(uint32_t*)&v1.x) : "f"(v1.x));
        asm("cvt.rna.tf32.f32 %0, %1;" : "=r"(*(uint32_t*)&v1.y) : "f"(v1.y));
        *reinterpret_cast<float2*>(g_aor + base0 + nt * 8) = v0;
        *reinterpret_cast<float2*>(g_aor + base1 + nt * 8) = v1;
    }
}

/* ------------------------------------------------------------------ */
extern "C" void kernel_launch(void* const* d_in, const int* in_sizes, int n_in,
                              void* d_out, int out_size)
{
    const float* x    = (const float*)d_in[0];
    /* d_in[1] = mask (static causal structure, unused) */
    const float* Wqkv = (const float*)d_in[2];
    const float* Wout = (const float*)d_in[3];
    float* out = (float*)d_out;

    float *xr, *wqr, *wor, *aor;
    cudaGetSymbolAddress((void**)&xr,  g_xr);
    cudaGetSymbolAddress((void**)&wqr, g_wqr);
    cudaGetSymbolAddress((void**)&wor, g_wor);
    cudaGetSymbolAddress((void**)&aor, g_aor);

    /* 0. pre-round inputs to tf32 (rna) */
    round_tf32<<<1024, 256>>>(x,    xr,  4096 * 1024 / 4);
    round_tf32<<<1024, 256>>>(Wqkv, wqr, 3072 * 1024 / 4);
    round_tf32<<<512,  256>>>(Wout, wor, 1024 * 1024 / 4);

    cudaFuncSetAttribute(gemm_tf32<0>,
                         cudaFuncAttributeMaxDynamicSharedMemorySize, GEMM_SMEM);
    cudaFuncSetAttribute(gemm_tf32<1>,
                         cudaFuncAttributeMaxDynamicSharedMemorySize, GEMM_SMEM);

    /* 1. QKV projection (tf32) -> q/k/v bf16 hi/lo (q pre-scaled) */
    gemm_tf32<0><<<dim3(3072 / 128, 4096 / 256), 512, GEMM_SMEM>>>(
        xr, wqr, nullptr, D_, 3 * D_);

    /* 2. causal flash attention (bf16 hi/lo) -> tf32-rounded ao */
    cudaFuncSetAttribute(attn_mma,
                         cudaFuncAttributeMaxDynamicSharedMemorySize, ATT_SMEM_BYTES);
    attn_mma<<<dim3((N_ / 128) * 32), 256, ATT_SMEM_BYTES>>>();

    /* 3. output projection (tf32) -> d_out (fp32) */
    gemm_tf32<1><<<dim3(1024 / 128, 4096 / 256), 512, GEMM_SMEM>>>(
        aor, wor, out, D_, D_);
}

// round 16
// speedup vs baseline: 1.1237x; 1.0410x over previous
#include <cuda_runtime.h>
#include <cuda_bf16.h>
#include <math.h>
#include <stdint.h>

#define B_ 2
#define N_ 2048
#define D_ 1024
#define H_ 16
#define DH_ 64
#define SCALE_ 0.125f   /* 64^-0.5, exact power of two */

/* ------------------------------------------------------------------ */
/* device scratch                                                      */
/* ------------------------------------------------------------------ */
__device__ float g_xr [4096 * 1024];   /* tf32-rounded x      */
__device__ float g_wqr[3072 * 1024];   /* tf32-rounded W_qkv  */
__device__ float g_wor[1024 * 1024];   /* tf32-rounded W_out  */
__device__ float g_q  [B_*H_*N_*DH_];  /* tf32-rounded, scaled q */
__device__ float g_k  [B_*H_*N_*DH_];  /* tf32-rounded k      */
__device__ __nv_bfloat16 g_vh[B_*H_*N_*DH_], g_vl[B_*H_*N_*DH_];
__device__ float         g_aor[B_*N_*D_];  /* tf32-rounded ao */

/* ------------------------------------------------------------------ */
/* helpers                                                             */
/* ------------------------------------------------------------------ */
__device__ __forceinline__ uint32_t smem_u32(const void* p) {
    uint32_t a;
    asm("{ .reg .u64 t; cvta.to.shared.u64 t, %1; cvt.u32.u64 %0, t; }"
        : "=r"(a) : "l"(p));
    return a;
}

/* swizzle for 128B-row fp32 tiles: chunk' = chunk ^ (row & 7) */
__device__ __forceinline__ uint32_t swzA(uint32_t o) {
    return o ^ (((o >> 7) & 7u) << 4);
}
/* swizzle for 256B-row fp32 tiles */
__device__ __forceinline__ uint32_t swzB(uint32_t o) {
    return o ^ (((o >> 8) & 7u) << 4);
}

__device__ __forceinline__ void ldsm4(uint32_t addr, uint32_t& r0, uint32_t& r1,
                                      uint32_t& r2, uint32_t& r3) {
    asm volatile("ldmatrix.sync.aligned.m8n8.x4.shared.b16 {%0,%1,%2,%3}, [%4];"
                 : "=r"(r0), "=r"(r1), "=r"(r2), "=r"(r3) : "r"(addr));
}

__device__ __forceinline__ void ldsm4t(uint32_t addr, uint32_t& r0, uint32_t& r1,
                                       uint32_t& r2, uint32_t& r3) {
    asm volatile("ldmatrix.sync.aligned.m8n8.x4.trans.shared.b16 {%0,%1,%2,%3}, [%4];"
                 : "=r"(r0), "=r"(r1), "=r"(r2), "=r"(r3) : "r"(addr));
}

__device__ __forceinline__ void mma16816(float* c,
                                         uint32_t a0, uint32_t a1, uint32_t a2, uint32_t a3,
                                         uint32_t b0, uint32_t b1) {
    asm volatile(
        "mma.sync.aligned.m16n8k16.row.col.f32.bf16.bf16.f32 "
        "{%0,%1,%2,%3}, {%4,%5,%6,%7}, {%8,%9}, {%0,%1,%2,%3};"
        : "+f"(c[0]), "+f"(c[1]), "+f"(c[2]), "+f"(c[3])
        : "r"(a0), "r"(a1), "r"(a2), "r"(a3), "r"(b0), "r"(b1));
}

__device__ __forceinline__ void mma_tf32(float* c,
                                         uint32_t a0, uint32_t a1, uint32_t a2, uint32_t a3,
                                         uint32_t b0, uint32_t b1) {
    asm volatile(
        "mma.sync.aligned.m16n8k8.row.col.f32.tf32.tf32.f32 "
        "{%0,%1,%2,%3}, {%4,%5,%6,%7}, {%8,%9}, {%0,%1,%2,%3};"
        : "+f"(c[0]), "+f"(c[1]), "+f"(c[2]), "+f"(c[3])
        : "r"(a0), "r"(a1), "r"(a2), "r"(a3), "r"(b0), "r"(b1));
}

__device__ __forceinline__ void split2(float x, float y, uint32_t& hi, uint32_t& lo) {
    __nv_bfloat162 h = __floats2bfloat162_rn(x, y);
    float rx = x - __bfloat162float(h.x);
    float ry = y - __bfloat162float(h.y);
    __nv_bfloat162 l = __floats2bfloat162_rn(rx, ry);
    hi = *reinterpret_cast<uint32_t*>(&h);
    lo = *reinterpret_cast<uint32_t*>(&l);
}

__device__ __forceinline__ void cp16(uint32_t saddr, const void* g) {
    asm volatile("cp.async.cg.shared.global [%0], [%1], 16;"
                 :: "r"(saddr), "l"(g) : "memory");
}

/* ---- mbarrier primitives (sm_90 generic) ---- */
__device__ __forceinline__ void mbar_init(uint32_t a, uint32_t cnt) {
    asm volatile("mbarrier.init.shared.b64 [%0], %1;" :: "r"(a), "r"(cnt) : "memory");
}
__device__ __forceinline__ void mbar_arrive(uint32_t a) {
    asm volatile("mbarrier.arrive.shared.b64 _, [%0];" :: "r"(a) : "memory");
}
__device__ __forceinline__ void cp_arrive(uint32_t a) {
    asm volatile("cp.async.mbarrier.arrive.noinc.shared.b64 [%0];"
                 :: "r"(a) : "memory");
}
__device__ __forceinline__ void mbar_wait(uint32_t a, uint32_t parity) {
    asm volatile(
        "{\n\t.reg .pred P;\n"
        "W_%=:\n\t"
        "mbarrier.try_wait.parity.acquire.cta.shared::cta.b64 P, [%0], %1;\n\t"
        "@P bra D_%=;\n\t"
        "bra W_%=;\n"
        "D_%=:\n\t}"
        :: "r"(a), "r"(parity) : "memory");
}

/* ------------------------------------------------------------------ */
/* round kernel: fp32 -> tf32-rounded fp32 (rna)                       */
/* ------------------------------------------------------------------ */
__global__ void __launch_bounds__(256)
round_tf32(const float* __restrict__ src, float* __restrict__ dst, int n4)
{
    int i      = blockIdx.x * blockDim.x + threadIdx.x;
    int stride = gridDim.x * blockDim.x;
    for (; i < n4; i += stride) {
        float4 v = reinterpret_cast<const float4*>(src)[i];
        float4 r;
        asm("cvt.rna.tf32.f32 %0, %1;" : "=r"(*(uint32_t*)&r.x) : "f"(v.x));
        asm("cvt.rna.tf32.f32 %0, %1;" : "=r"(*(uint32_t*)&r.y) : "f"(v.y));
        asm("cvt.rna.tf32.f32 %0, %1;" : "=r"(*(uint32_t*)&r.z) : "f"(v.z));
        asm("cvt.rna.tf32.f32 %0, %1;" : "=r"(*(uint32_t*)&r.w) : "f"(v.w));
        reinterpret_cast<float4*>(dst)[i] = r;
    }
}

/* ------------------------------------------------------------------ */
/* TF32 HMMA GEMM (R15, unchanged): C = A * W^T.                       */
/* CTA tile 256x128, BK=32, 512 thr, 4-stage mbarrier pipeline.        */
/* MODE 0: q/k -> tf32 fp32 (q scaled), v -> bf16 hi/lo. MODE 1: fp32. */
/* ------------------------------------------------------------------ */
#define GARR_A (256 * 128u)
#define GARR_W (128 * 128u)
#define GSTAGE_B (GARR_A + GARR_W)
#define GSTAGES 4
#define GEMM_SMEM (128 + GSTAGES * GSTAGE_B)

template <int MODE>
__global__ void __launch_bounds__(512, 1)
gemm_tf32(const float* __restrict__ A, const float* __restrict__ W,
          float* __restrict__ C, int K, int Nout)
{
    extern __shared__ float smem[];
    const uint32_t sb = smem_u32(smem);
    const uint32_t MBF = sb;
    const uint32_t MBE = sb + 32;
    const uint32_t DB  = sb + 128;

    const int tid  = threadIdx.x;
    const int lane = tid & 31;
    const int wid  = tid >> 5;
    const int wm   = wid & 3;
    const int wn   = wid >> 2;

    const int m0 = blockIdx.y * 256;
    const int j0 = blockIdx.x * 128;

    if (tid == 0) {
#pragma unroll
        for (int s = 0; s < GSTAGES; s++) {
            mbar_init(MBF + s * 8, 512);
            mbar_init(MBE + s * 8, 512);
        }
    }
    __syncthreads();

    const int q0 = tid & 7;

#define ISSUE_CHUNK(kc, stage)                                                \
    do {                                                                      \
        const int koff = (kc) * 32;                                          \
        const uint32_t st_ = DB + (uint32_t)(stage) * GSTAGE_B;              \
        _Pragma("unroll")                                                     \
        for (int i_ = 0; i_ < 4; i_++) {                                     \
            int r_ = (tid + i_ * 512) >> 3;                                  \
            uint32_t so_ = swzA((uint32_t)(r_ * 128 + q0 * 16));             \
            cp16(st_ + so_, A + (size_t)(m0 + r_) * K + koff + q0 * 4);      \
        }                                                                     \
        _Pragma("unroll")                                                     \
        for (int i_ = 0; i_ < 2; i_++) {                                     \
            int r_ = (tid + i_ * 512) >> 3;                                  \
            uint32_t so_ = swzA((uint32_t)(r_ * 128 + q0 * 16));             \
            cp16(st_ + GARR_A + so_, W + (size_t)(j0 + r_) * K + koff + q0 * 4); \
        }                                                                     \
        cp_arrive(MBF + (stage) * 8);                                        \
    } while (0)

    const int a_r8 = lane & 7;
    const int a_rh = (lane >> 3) & 1;
    const int a_ch = lane >> 4;
    const int b_rh = lane >> 4;
    const int b_ch = (lane >> 3) & 1;

    float acc[4][4][4];
#pragma unroll
    for (int i = 0; i < 4; i++)
#pragma unroll
        for (int j = 0; j < 4; j++)
#pragma unroll
            for (int c = 0; c < 4; c++) acc[i][j][c] = 0.f;

    const int nchunk = K >> 5;

    ISSUE_CHUNK(0, 0);
    ISSUE_CHUNK(1, 1);
    ISSUE_CHUNK(2, 2);

    for (int kc = 0; kc < nchunk; kc++) {
        const int s = kc & 3;
        if (kc + 3 < nchunk) {
            const int s2 = (kc + 3) & 3;
            if (kc >= 1) mbar_wait(MBE + s2 * 8, (uint32_t)(((kc - 1) >> 2) & 1));
            ISSUE_CHUNK(kc + 3, s2);
        }

        mbar_wait(MBF + s * 8, (uint32_t)((kc >> 2) & 1));

        const uint32_t stg = DB + (uint32_t)s * GSTAGE_B;
        const uint32_t sA  = stg;
        const uint32_t sW  = stg + GARR_A;

#pragma unroll
        for (int ks = 0; ks < 4; ks++) {
            uint32_t a[4][4];
#pragma unroll
            for (int mt = 0; mt < 4; mt++) {
                int row   = wm * 64 + mt * 16 + a_r8 + a_rh * 8;
                int chunk = ks * 2 + a_ch;
                uint32_t addr = sA + swzA((uint32_t)(row * 128 + chunk * 16));
                ldsm4(addr, a[mt][0], a[mt][1], a[mt][2], a[mt][3]);
            }
#pragma unroll
            for (int np = 0; np < 2; np++) {
                int row   = wn * 32 + np * 16 + a_r8 + b_rh * 8;
                int chunk = ks * 2 + b_ch;
                uint32_t addr = sW + swzA((uint32_t)(row * 128 + chunk * 16));
                uint32_t bfr[4];
                ldsm4(addr, bfr[0], bfr[1], bfr[2], bfr[3]);
#pragma unroll
                for (int mt = 0; mt < 4; mt++) {
                    mma_tf32(acc[mt][np * 2 + 0], a[mt][0], a[mt][1], a[mt][2], a[mt][3],
                             bfr[0], bfr[1]);
                    mma_tf32(acc[mt][np * 2 + 1], a[mt][0], a[mt][1], a[mt][2], a[mt][3],
                             bfr[2], bfr[3]);
                }
            }
        }
        mbar_arrive(MBE + s * 8);
    }

    /* epilogue */
    const int grp = lane >> 2;
    const int qid = lane & 3;
#pragma unroll
    for (int mt = 0; mt < 4; mt++) {
#pragma unroll
        for (int nt = 0; nt < 4; nt++) {
            const float* c = acc[mt][nt];
            int row = m0 + wm * 64 + mt * 16 + grp;
            int col = j0 + wn * 32 + nt * 8 + qid * 2;
#pragma unroll
            for (int half = 0; half < 2; half++) {
                int m = row + half * 8;
                float vx = c[half * 2], vy = c[half * 2 + 1];
                if (MODE == 0) {
                    int s  = col >> 10;
                    int rr = col & 1023;
                    int h  = rr >> 6;
                    int dh = rr & 63;
                    int b  = m >> 11;
                    int n  = m & 2047;
                    size_t idx = (((size_t)(b * H_ + h) * N_ + n) * DH_ + dh);
                    if (s == 2) {
                        uint32_t hi, lo;
                        split2(vx, vy, hi, lo);
                        *reinterpret_cast<uint32_t*>(g_vh + idx) = hi;
                        *reinterpret_cast<uint32_t*>(g_vl + idx) = lo;
                    } else {
                        float sc = (s == 0) ? SCALE_ : 1.f;
                        float2 v = make_float2(vx * sc, vy * sc);
                        asm("cvt.rna.tf32.f32 %0, %1;"
                            : "=r"(*(uint32_t*)&v.x) : "f"(v.x));
                        asm("cvt.rna.tf32.f32 %0, %1;"
                            : "=r"(*(uint32_t*)&v.y) : "f"(v.y));
                        float* dst = (s == 0) ? g_q : g_k;
                        *reinterpret_cast<float2*>(dst + idx) = v;
                    }
                } else {
                    *reinterpret_cast<float2*>(C + (size_t)m * Nout + col) =
                        make_float2(vx, vy);
                }
            }
        }
    }
}

/* ------------------------------------------------------------------ */
/* Flash-attention: S = QK^T in single-pass TF32 (q,k tf32 fp32);      */
/* P·V in bf16 hi/lo 3-split. 2-stage KV mbarrier pipeline; skip-warp  */
/* fast path. 2 CTAs/SM. Epilogue: tf32-rounded ao.                    */
/* smem bytes: 128 mbar + Q 32768 + 2 * (K 16384 + VH 9216 + VL 9216)  */
/* ------------------------------------------------------------------ */
#define ASTR 72
#define SMQ_B   128u
#define SMST0_B (SMQ_B + 32768u)
#define KST_B   16384u
#define VH_OFF  16384u
#define VL_OFF  (16384u + 9216u)
#define STG_B   (16384u + 2u * 9216u)        /* 34816 per stage */
#define ATT_SMEM_BYTES (SMST0_B + 2 * STG_B) /* 102528 B        */

__global__ void __launch_bounds__(256, 2)
attn_mma()
{
    extern __shared__ char sraw[];
    const uint32_t sb0 = smem_u32(sraw);
    const uint32_t MBF = sb0;
    const uint32_t MBE = sb0 + 16;
    const uint32_t sQ  = sb0 + SMQ_B;

    const int qt = (N_ / 128 - 1) - (blockIdx.x >> 5);  /* heavy tiles first */
    const int bh = blockIdx.x & 31;
    const int b  = bh >> 4;
    const int h  = bh & 15;

    const int tid  = threadIdx.x;
    const int lane = tid & 31;
    const int w    = tid >> 5;

    const float* Qb = g_q + (size_t)bh * N_ * DH_;
    const float* Kb = g_k + (size_t)bh * N_ * DH_;
    const __nv_bfloat16* Vbh = g_vh + (size_t)bh * N_ * DH_;
    const __nv_bfloat16* Vbl = g_vl + (size_t)bh * N_ * DH_;

    if (tid == 0) {
#pragma unroll
        for (int s = 0; s < 2; s++) {
            mbar_init(MBF + s * 8, 256);
            mbar_init(MBE + s * 8, 256);
        }
    }
    __syncthreads();

    /* K copy slots: 16 chunks (16B) per 256B row */
    const int kqr = tid >> 4;            /* rows 0..15 per pass  */
    const int kqc = tid & 15;            /* chunk 0..15          */
    /* V copy slots (bf16, ASTR stride) */
    const int vr0 = tid >> 3;
    const int vc8 = (tid & 7) * 8;
    const uint32_t vso0 = (uint32_t)(vr0 * ASTR + vc8) * 2;
    const uint32_t vso1 = (uint32_t)((vr0 + 32) * ASTR + vc8) * 2;

#define ISSUE_KV(jt, stage)                                                   \
    do {                                                                      \
        const uint32_t st_ = sb0 + SMST0_B + (uint32_t)(stage) * STG_B;      \
        _Pragma("unroll")                                                     \
        for (int i_ = 0; i_ < 4; i_++) {                                     \
            int r_ = kqr + i_ * 16;                                          \
            uint32_t so_ = swzB((uint32_t)(r_ * 256 + kqc * 16));            \
            cp16(st_ + so_, Kb + (size_t)((jt) * 64 + r_) * DH_ + kqc * 4);  \
        }                                                                     \
        {                                                                     \
            const size_t g0 = (size_t)((jt) * 64 + vr0) * DH_ + vc8;         \
            const size_t g1 = (size_t)((jt) * 64 + vr0 + 32) * DH_ + vc8;    \
            cp16(st_ + VH_OFF + vso0, Vbh + g0);                             \
            cp16(st_ + VH_OFF + vso1, Vbh + g1);                             \
            cp16(st_ + VL_OFF + vso0, Vbl + g0);                             \
            cp16(st_ + VL_OFF + vso1, Vbl + g1);                             \
        }                                                                     \
        cp_arrive(MBF + (stage) * 8);                                        \
    } while (0)

    ISSUE_KV(0, 0);

    /* ---- load Q tile (tf32 fp32, pre-scaled): 128 rows x 256 B ---- */
#pragma unroll
    for (int it = 0; it < 8; it++) {
        int idx = tid + it * 256;
        int r   = idx >> 4;
        int c   = idx & 15;
        uint32_t so = swzB((uint32_t)(r * 256 + c * 16));
        *reinterpret_cast<uint4*>(sraw + SMQ_B + so) =
            *reinterpret_cast<const uint4*>(Qb + (size_t)(qt * 128 + r) * DH_ + c * 4);
    }
    __syncthreads();

    /* ---- Q tf32 A-fragments (8 k8-steps) into registers ---- */
    const int a_r8 = lane & 7;
    const int a_rh = (lane >> 3) & 1;
    const int a_ch = lane >> 4;
    const int b_rh = lane >> 4;
    const int b_ch = (lane >> 3) & 1;

    uint32_t qf[8][4];
    {
        const int qrow = w * 16 + a_r8 + a_rh * 8;
#pragma unroll
        for (int ks = 0; ks < 8; ks++) {
            int chunk = ks * 2 + a_ch;
            uint32_t addr = sQ + swzB((uint32_t)(qrow * 256 + chunk * 16));
            ldsm4(addr, qf[ks][0], qf[ks][1], qf[ks][2], qf[ks][3]);
        }
    }

    const uint32_t vpat = 2u * ((uint32_t)((lane & 15) * ASTR) + ((lane & 16) >> 1));

    float o[8][4];
#pragma unroll
    for (int i = 0; i < 8; i++)
#pragma unroll
        for (int c = 0; c < 4; c++) o[i][c] = 0.f;
    float mrow0 = -INFINITY, mrow1 = -INFINITY;
    float lrow0 = 0.f, lrow1 = 0.f;

    const int qglo   = qt * 128 + w * 16;
    const int ntiles = 2 * qt + 2;

    for (int jt = 0; jt < ntiles; jt++) {
        const int s = jt & 1;
        if (jt + 1 < ntiles) {
            const int s2 = (jt + 1) & 1;
            if (jt >= 1) mbar_wait(MBE + s2 * 8, (uint32_t)(((jt - 1) >> 1) & 1));
            ISSUE_KV(jt + 1, s2);
        }

        if (jt * 64 > qglo + 15) {        /* skip-warp fast path */
            mbar_arrive(MBE + s * 8);
            continue;
        }

        mbar_wait(MBF + s * 8, (uint32_t)((jt >> 1) & 1));

        {
            const uint32_t stg = sb0 + SMST0_B + (uint32_t)s * STG_B;
            const uint32_t sK  = stg;
            const uint32_t sVH = stg + VH_OFF;
            const uint32_t sVL = stg + VL_OFF;

            /* ---- S = Q K^T  (single-pass tf32: 8 k8-steps) ---- */
            float sfr[8][4];
#pragma unroll
            for (int i = 0; i < 8; i++)
#pragma unroll
                for (int c = 0; c < 4; c++) sfr[i][c] = 0.f;

#pragma unroll
            for (int ks = 0; ks < 8; ks++) {
#pragma unroll
                for (int np = 0; np < 4; np++) {
                    int row   = np * 16 + a_r8 + b_rh * 8;
                    int chunk = ks * 2 + b_ch;
                    uint32_t addr = sK + swzB((uint32_t)(row * 256 + chunk * 16));
                    uint32_t bfr[4];
                    ldsm4(addr, bfr[0], bfr[1], bfr[2], bfr[3]);
                    mma_tf32(sfr[np * 2 + 0], qf[ks][0], qf[ks][1], qf[ks][2], qf[ks][3],
                             bfr[0], bfr[1]);
                    mma_tf32(sfr[np * 2 + 1], qf[ks][0], qf[ks][1], qf[ks][2], qf[ks][3],
                             bfr[2], bfr[3]);
                }
            }

            /* ---- causal mask ---- */
            const int r0 = qglo + (lane >> 2);
            const int r1 = r0 + 8;
            if (jt * 64 + 63 > qglo) {
                const int colb = jt * 64 + (lane & 3) * 2;
#pragma unroll
                for (int nt = 0; nt < 8; nt++) {
                    int c0 = colb + nt * 8;
                    if (c0 > r0)     sfr[nt][0] = -INFINITY;
                    if (c0 + 1 > r0) sfr[nt][1] = -INFINITY;
                    if (c0 > r1)     sfr[nt][2] = -INFINITY;
                    if (c0 + 1 > r1) sfr[nt][3] = -INFINITY;
                }
            }

            /* ---- online softmax ---- */
            float mt0 = sfr[0][0], mt1 = sfr[0][2];
#pragma unroll
            for (int nt = 0; nt < 8; nt++) {
                mt0 = fmaxf(mt0, fmaxf(sfr[nt][0], sfr[nt][1]));
                mt1 = fmaxf(mt1, fmaxf(sfr[nt][2], sfr[nt][3]));
            }
            mt0 = fmaxf(mt0, __shfl_xor_sync(0xffffffffu, mt0, 1));
            mt0 = fmaxf(mt0, __shfl_xor_sync(0xffffffffu, mt0, 2));
            mt1 = fmaxf(mt1, __shfl_xor_sync(0xffffffffu, mt1, 1));
            mt1 = fmaxf(mt1, __shfl_xor_sync(0xffffffffu, mt1, 2));

            const float mn0 = fmaxf(mrow0, mt0);
            const float mn1 = fmaxf(mrow1, mt1);
            const float al0 = __expf(mrow0 - mn0);
            const float al1 = __expf(mrow1 - mn1);

            float ps0 = 0.f, ps1 = 0.f;
#pragma unroll
            for (int nt = 0; nt < 8; nt++) {
                sfr[nt][0] = __expf(sfr[nt][0] - mn0);
                sfr[nt][1] = __expf(sfr[nt][1] - mn0);
                sfr[nt][2] = __expf(sfr[nt][2] - mn1);
                sfr[nt][3] = __expf(sfr[nt][3] - mn1);
                ps0 += sfr[nt][0] + sfr[nt][1];
                ps1 += sfr[nt][2] + sfr[nt][3];
            }
            ps0 += __shfl_xor_sync(0xffffffffu, ps0, 1);
            ps0 += __shfl_xor_sync(0xffffffffu, ps0, 2);
            ps1 += __shfl_xor_sync(0xffffffffu, ps1, 1);
            ps1 += __shfl_xor_sync(0xffffffffu, ps1, 2);

            lrow0 = lrow0 * al0 + ps0;
            lrow1 = lrow1 * al1 + ps1;
#pragma unroll
            for (int nt = 0; nt < 8; nt++) {
                o[nt][0] *= al0; o[nt][1] *= al0;
                o[nt][2] *= al1; o[nt][3] *= al1;
            }
            mrow0 = mn0;
            mrow1 = mn1;

            /* ---- O += P V (bf16 hi/lo 3-split; V via ldmatrix.trans) ---- */
#pragma unroll
            for (int ks = 0; ks < 4; ks++) {
                uint32_t ph[4], pl[4];
                split2(sfr[2 * ks][0],     sfr[2 * ks][1],     ph[0], pl[0]);
                split2(sfr[2 * ks][2],     sfr[2 * ks][3],     ph[1], pl[1]);
                split2(sfr[2 * ks + 1][0], sfr[2 * ks + 1][1], ph[2], pl[2]);
                split2(sfr[2 * ks + 1][2], sfr[2 * ks + 1][3], ph[3], pl[3]);
#pragma unroll
                for (int np = 0; np < 4; np++) {
                    const uint32_t voff = vpat + 2u * (ks * 16 * ASTR + np * 16);
                    uint32_t bh4[4], bl4[4];
                    ldsm4t(sVH + voff, bh4[0], bh4[1], bh4[2], bh4[3]);
                    ldsm4t(sVL + voff, bl4[0], bl4[1], bl4[2], bl4[3]);
#pragma unroll
                    for (int sub = 0; sub < 2; sub++) {
                        float* c = o[np * 2 + sub];
                        mma16816(c, ph[0], ph[1], ph[2], ph[3],
                                 bh4[sub * 2], bh4[sub * 2 + 1]);
                        mma16816(c, ph[0], ph[1], ph[2], ph[3],
                                 bl4[sub * 2], bl4[sub * 2 + 1]);
                        mma16816(c, pl[0], pl[1], pl[2], pl[3],
                                 bh4[sub * 2], bh4[sub * 2 + 1]);
                    }
                }
            }
        }

        mbar_arrive(MBE + s * 8);
    }

    /* ---- epilogue: normalize, write tf32-rounded ao ---- */
    const float i0 = 1.f / lrow0;
    const float i1 = 1.f / lrow1;
    const int r0 = qt * 128 + w * 16 + (lane >> 2);
    const size_t base0 = ((size_t)b * N_ + r0) * D_ + h * DH_ + (lane & 3) * 2;
    const size_t base1 = base0 + 8 * D_;
#pragma unroll
    for (int nt = 0; nt < 8; nt++) {
        float2 v0 = make_float2(o[nt][0] * i0, o[nt][1] * i0);
        float2 v1 = make_float2(o[nt][2] * i1, o[nt][3] * i1);
        asm("cvt.rna.tf32.f32 %0, %1;" : "=r"(*(uint32_t*)&v0.x) : "f"(v0.x));
        asm("cvt.rna.tf32.f32 %0, %1;" : "=r"(*(uint32_t*)&v0.y) : "f"(v0.y));
        asm("cvt.rna.tf32.f32 %0, %1;" : "=r"(*(uint32_t*)&v1.x) : "f"(v1.x));
        asm("cvt.rna.tf32.f32 %0, %1;" : "=r"(*(uint32_t*)&v1.y) : "f"(v1.y));
        *reinterpret_cast<float2*>(g_aor + base0 + nt * 8) = v0;
        *reinterpret_cast<float2*>(g_aor + base1 + nt * 8) = v1;
    }
}

/* ------------------------------------------------------------------ */
extern "C" void kernel_launch(void* const* d_in, const int* in_sizes, int n_in,
                              void* d_out, int out_size)
{
    const float* x    = (const float*)d_in[0];
    /* d_in[1] = mask (static causal structure, unused) */
    const float* Wqkv = (const float*)d_in[2];
    const float* Wout = (const float*)d_in[3];
    float* out = (float*)d_out;

    float *xr, *wqr, *wor, *aor;
    cudaGetSymbolAddress((void**)&xr,  g_xr);
    cudaGetSymbolAddress((void**)&wqr, g_wqr);
    cudaGetSymbolAddress((void**)&wor, g_wor);
    cudaGetSymbolAddress((void**)&aor, g_aor);

    /* 0. pre-round inputs to tf32 (rna) */
    round_tf32<<<1024, 256>>>(x,    xr,  4096 * 1024 / 4);
    round_tf32<<<1024, 256>>>(Wqkv, wqr, 3072 * 1024 / 4);
    round_tf32<<<512,  256>>>(Wout, wor, 1024 * 1024 / 4);

    cudaFuncSetAttribute(gemm_tf32<0>,
                         cudaFuncAttributeMaxDynamicSharedMemorySize, GEMM_SMEM);
    cudaFuncSetAttribute(gemm_tf32<1>,
                         cudaFuncAttributeMaxDynamicSharedMemorySize, GEMM_SMEM);

    /* 1. QKV projection (tf32) -> q/k tf32 fp32 (q scaled), v bf16 hi/lo */
    gemm_tf32<0><<<dim3(3072 / 128, 4096 / 256), 512, GEMM_SMEM>>>(
        xr, wqr, nullptr, D_, 3 * D_);

    /* 2. causal flash attention (S: tf32; PV: bf16 split) -> tf32 ao */
    cudaFuncSetAttribute(attn_mma,
                         cudaFuncAttributeMaxDynamicSharedMemorySize, ATT_SMEM_BYTES);
    attn_mma<<<dim3((N_ / 128) * 32), 256, ATT_SMEM_BYTES>>>();

    /* 3. output projection (tf32) -> d_out (fp32) */
    gemm_tf32<1><<<dim3(1024 / 128, 4096 / 256), 512, GEMM_SMEM>>>(
        aor, wor, out, D_, D_);
}

// round 17
// speedup vs baseline: 1.1339x; 1.0090x over previous
#include <cuda_runtime.h>
#include <cuda_bf16.h>
#include <math.h>
#include <stdint.h>

#define B_ 2
#define N_ 2048
#define D_ 1024
#define H_ 16
#define DH_ 64
#define SCALE_ 0.125f   /* 64^-0.5, exact power of two */

/* ------------------------------------------------------------------ */
/* device scratch                                                      */
/* ------------------------------------------------------------------ */
__device__ float g_xr [4096 * 1024];   /* tf32-rounded x      */
__device__ float g_wqr[3072 * 1024];   /* tf32-rounded W_qkv  */
__device__ float g_wor[1024 * 1024];   /* tf32-rounded W_out  */
__device__ float g_q  [B_*H_*N_*DH_];  /* tf32-rounded, scaled q */
__device__ float g_k  [B_*H_*N_*DH_];  /* tf32-rounded k      */
__device__ __nv_bfloat16 g_vh[B_*H_*N_*DH_], g_vl[B_*H_*N_*DH_];
__device__ float         g_aor[B_*N_*D_];  /* tf32-rounded ao */

/* ------------------------------------------------------------------ */
/* helpers                                                             */
/* ------------------------------------------------------------------ */
__device__ __forceinline__ uint32_t smem_u32(const void* p) {
    uint32_t a;
    asm("{ .reg .u64 t; cvta.to.shared.u64 t, %1; cvt.u32.u64 %0, t; }"
        : "=r"(a) : "l"(p));
    return a;
}

/* swizzle for 128B-row fp32 tiles: chunk' = chunk ^ (row & 7) */
__device__ __forceinline__ uint32_t swzA(uint32_t o) {
    return o ^ (((o >> 7) & 7u) << 4);
}
/* swizzle for 256B-row fp32 tiles */
__device__ __forceinline__ uint32_t swzB(uint32_t o) {
    return o ^ (((o >> 8) & 7u) << 4);
}

__device__ __forceinline__ void ldsm4(uint32_t addr, uint32_t& r0, uint32_t& r1,
                                      uint32_t& r2, uint32_t& r3) {
    asm volatile("ldmatrix.sync.aligned.m8n8.x4.shared.b16 {%0,%1,%2,%3}, [%4];"
                 : "=r"(r0), "=r"(r1), "=r"(r2), "=r"(r3) : "r"(addr));
}

__device__ __forceinline__ void ldsm4t(uint32_t addr, uint32_t& r0, uint32_t& r1,
                                       uint32_t& r2, uint32_t& r3) {
    asm volatile("ldmatrix.sync.aligned.m8n8.x4.trans.shared.b16 {%0,%1,%2,%3}, [%4];"
                 : "=r"(r0), "=r"(r1), "=r"(r2), "=r"(r3) : "r"(addr));
}

__device__ __forceinline__ void mma16816(float* c,
                                         uint32_t a0, uint32_t a1, uint32_t a2, uint32_t a3,
                                         uint32_t b0, uint32_t b1) {
    asm volatile(
        "mma.sync.aligned.m16n8k16.row.col.f32.bf16.bf16.f32 "
        "{%0,%1,%2,%3}, {%4,%5,%6,%7}, {%8,%9}, {%0,%1,%2,%3};"
        : "+f"(c[0]), "+f"(c[1]), "+f"(c[2]), "+f"(c[3])
        : "r"(a0), "r"(a1), "r"(a2), "r"(a3), "r"(b0), "r"(b1));
}

__device__ __forceinline__ void mma_tf32(float* c,
                                         uint32_t a0, uint32_t a1, uint32_t a2, uint32_t a3,
                                         uint32_t b0, uint32_t b1) {
    asm volatile(
        "mma.sync.aligned.m16n8k8.row.col.f32.tf32.tf32.f32 "
        "{%0,%1,%2,%3}, {%4,%5,%6,%7}, {%8,%9}, {%0,%1,%2,%3};"
        : "+f"(c[0]), "+f"(c[1]), "+f"(c[2]), "+f"(c[3])
        : "r"(a0), "r"(a1), "r"(a2), "r"(a3), "r"(b0), "r"(b1));
}

__device__ __forceinline__ void split2(float x, float y, uint32_t& hi, uint32_t& lo) {
    __nv_bfloat162 h = __floats2bfloat162_rn(x, y);
    float rx = x - __bfloat162float(h.x);
    float ry = y - __bfloat162float(h.y);
    __nv_bfloat162 l = __floats2bfloat162_rn(rx, ry);
    hi = *reinterpret_cast<uint32_t*>(&h);
    lo = *reinterpret_cast<uint32_t*>(&l);
}

__device__ __forceinline__ void cp16(uint32_t saddr, const void* g) {
    asm volatile("cp.async.cg.shared.global [%0], [%1], 16;"
                 :: "r"(saddr), "l"(g) : "memory");
}

/* ---- mbarrier primitives (sm_90 generic) ---- */
__device__ __forceinline__ void mbar_init(uint32_t a, uint32_t cnt) {
    asm volatile("mbarrier.init.shared.b64 [%0], %1;" :: "r"(a), "r"(cnt) : "memory");
}
__device__ __forceinline__ void mbar_arrive(uint32_t a) {
    asm volatile("mbarrier.arrive.shared.b64 _, [%0];" :: "r"(a) : "memory");
}
__device__ __forceinline__ void cp_arrive(uint32_t a) {
    asm volatile("cp.async.mbarrier.arrive.noinc.shared.b64 [%0];"
                 :: "r"(a) : "memory");
}
__device__ __forceinline__ void mbar_wait(uint32_t a, uint32_t parity) {
    asm volatile(
        "{\n\t.reg .pred P;\n"
        "W_%=:\n\t"
        "mbarrier.try_wait.parity.acquire.cta.shared::cta.b64 P, [%0], %1;\n\t"
        "@P bra D_%=;\n\t"
        "bra W_%=;\n"
        "D_%=:\n\t}"
        :: "r"(a), "r"(parity) : "memory");
}

/* ------------------------------------------------------------------ */
/* fused rounding kernel: all three inputs -> tf32-rounded fp32        */
/* ------------------------------------------------------------------ */
#define NX4  (4096 * 1024 / 4)
#define NWQ4 (3072 * 1024 / 4)
#define NWO4 (1024 * 1024 / 4)

__global__ void __launch_bounds__(256)
round_all(const float* __restrict__ x, const float* __restrict__ wq,
          const float* __restrict__ wo)
{
    const int total = NX4 + NWQ4 + NWO4;
    int i      = blockIdx.x * blockDim.x + threadIdx.x;
    int stride = gridDim.x * blockDim.x;
    for (; i < total; i += stride) {
        const float4* src;
        float4* dst;
        int j = i;
        if (j < NX4) {
            src = reinterpret_cast<const float4*>(x) + j;
            dst = reinterpret_cast<float4*>(g_xr) + j;
        } else if ((j -= NX4) < NWQ4) {
            src = reinterpret_cast<const float4*>(wq) + j;
            dst = reinterpret_cast<float4*>(g_wqr) + j;
        } else {
            j -= NWQ4;
            src = reinterpret_cast<const float4*>(wo) + j;
            dst = reinterpret_cast<float4*>(g_wor) + j;
        }
        float4 v = *src;
        float4 r;
        asm("cvt.rna.tf32.f32 %0, %1;" : "=r"(*(uint32_t*)&r.x) : "f"(v.x));
        asm("cvt.rna.tf32.f32 %0, %1;" : "=r"(*(uint32_t*)&r.y) : "f"(v.y));
        asm("cvt.rna.tf32.f32 %0, %1;" : "=r"(*(uint32_t*)&r.z) : "f"(v.z));
        asm("cvt.rna.tf32.f32 %0, %1;" : "=r"(*(uint32_t*)&r.w) : "f"(v.w));
        *dst = r;
    }
}

/* ------------------------------------------------------------------ */
/* TF32 HMMA GEMM (QKV): CTA tile 256x128, BK=32, 512 thr, 4-stage     */
/* mbarrier pipeline. Epilogue -> q/k tf32 fp32 (q scaled), v bf16.    */
/* ------------------------------------------------------------------ */
#define GARR_A (256 * 128u)
#define GARR_W (128 * 128u)
#define GSTAGE_B (GARR_A + GARR_W)
#define GSTAGES 4
#define GEMM_SMEM (128 + GSTAGES * GSTAGE_B)

__global__ void __launch_bounds__(512, 1)
gemm_qkv(const float* __restrict__ A, const float* __restrict__ W, int K)
{
    extern __shared__ float smem[];
    const uint32_t sb = smem_u32(smem);
    const uint32_t MBF = sb;
    const uint32_t MBE = sb + 32;
    const uint32_t DB  = sb + 128;

    const int tid  = threadIdx.x;
    const int lane = tid & 31;
    const int wid  = tid >> 5;
    const int wm   = wid & 3;
    const int wn   = wid >> 2;

    const int m0 = blockIdx.y * 256;
    const int j0 = blockIdx.x * 128;

    if (tid == 0) {
#pragma unroll
        for (int s = 0; s < GSTAGES; s++) {
            mbar_init(MBF + s * 8, 512);
            mbar_init(MBE + s * 8, 512);
        }
    }
    __syncthreads();

    const int q0 = tid & 7;

#define ISSUE_CHUNK(kc, stage)                                                \
    do {                                                                      \
        const int koff = (kc) * 32;                                          \
        const uint32_t st_ = DB + (uint32_t)(stage) * GSTAGE_B;              \
        _Pragma("unroll")                                                     \
        for (int i_ = 0; i_ < 4; i_++) {                                     \
            int r_ = (tid + i_ * 512) >> 3;                                  \
            uint32_t so_ = swzA((uint32_t)(r_ * 128 + q0 * 16));             \
            cp16(st_ + so_, A + (size_t)(m0 + r_) * K + koff + q0 * 4);      \
        }                                                                     \
        _Pragma("unroll")                                                     \
        for (int i_ = 0; i_ < 2; i_++) {                                     \
            int r_ = (tid + i_ * 512) >> 3;                                  \
            uint32_t so_ = swzA((uint32_t)(r_ * 128 + q0 * 16));             \
            cp16(st_ + GARR_A + so_, W + (size_t)(j0 + r_) * K + koff + q0 * 4); \
        }                                                                     \
        cp_arrive(MBF + (stage) * 8);                                        \
    } while (0)

    const int a_r8 = lane & 7;
    const int a_rh = (lane >> 3) & 1;
    const int a_ch = lane >> 4;
    const int b_rh = lane >> 4;
    const int b_ch = (lane >> 3) & 1;

    float acc[4][4][4];
#pragma unroll
    for (int i = 0; i < 4; i++)
#pragma unroll
        for (int j = 0; j < 4; j++)
#pragma unroll
            for (int c = 0; c < 4; c++) acc[i][j][c] = 0.f;

    const int nchunk = K >> 5;

    ISSUE_CHUNK(0, 0);
    ISSUE_CHUNK(1, 1);
    ISSUE_CHUNK(2, 2);

    for (int kc = 0; kc < nchunk; kc++) {
        const int s = kc & 3;
        if (kc + 3 < nchunk) {
            const int s2 = (kc + 3) & 3;
            if (kc >= 1) mbar_wait(MBE + s2 * 8, (uint32_t)(((kc - 1) >> 2) & 1));
            ISSUE_CHUNK(kc + 3, s2);
        }

        mbar_wait(MBF + s * 8, (uint32_t)((kc >> 2) & 1));

        const uint32_t stg = DB + (uint32_t)s * GSTAGE_B;
        const uint32_t sA  = stg;
        const uint32_t sW  = stg + GARR_A;

#pragma unroll
        for (int ks = 0; ks < 4; ks++) {
            uint32_t a[4][4];
#pragma unroll
            for (int mt = 0; mt < 4; mt++) {
                int row   = wm * 64 + mt * 16 + a_r8 + a_rh * 8;
                int chunk = ks * 2 + a_ch;
                uint32_t addr = sA + swzA((uint32_t)(row * 128 + chunk * 16));
                ldsm4(addr, a[mt][0], a[mt][1], a[mt][2], a[mt][3]);
            }
#pragma unroll
            for (int np = 0; np < 2; np++) {
                int row   = wn * 32 + np * 16 + a_r8 + b_rh * 8;
                int chunk = ks * 2 + b_ch;
                uint32_t addr = sW + swzA((uint32_t)(row * 128 + chunk * 16));
                uint32_t bfr[4];
                ldsm4(addr, bfr[0], bfr[1], bfr[2], bfr[3]);
#pragma unroll
                for (int mt = 0; mt < 4; mt++) {
                    mma_tf32(acc[mt][np * 2 + 0], a[mt][0], a[mt][1], a[mt][2], a[mt][3],
                             bfr[0], bfr[1]);
                    mma_tf32(acc[mt][np * 2 + 1], a[mt][0], a[mt][1], a[mt][2], a[mt][3],
                             bfr[2], bfr[3]);
                }
            }
        }
        mbar_arrive(MBE + s * 8);
    }

    /* epilogue -> q/k tf32 fp32, v bf16 hi/lo */
    const int grp = lane >> 2;
    const int qid = lane & 3;
#pragma unroll
    for (int mt = 0; mt < 4; mt++) {
#pragma unroll
        for (int nt = 0; nt < 4; nt++) {
            const float* c = acc[mt][nt];
            int row = m0 + wm * 64 + mt * 16 + grp;
            int col = j0 + wn * 32 + nt * 8 + qid * 2;
#pragma unroll
            for (int half = 0; half < 2; half++) {
                int m = row + half * 8;
                float vx = c[half * 2], vy = c[half * 2 + 1];
                int s  = col >> 10;
                int rr = col & 1023;
                int h  = rr >> 6;
                int dh = rr & 63;
                int b  = m >> 11;
                int n  = m & 2047;
                size_t idx = (((size_t)(b * H_ + h) * N_ + n) * DH_ + dh);
                if (s == 2) {
                    uint32_t hi, lo;
                    split2(vx, vy, hi, lo);
                    *reinterpret_cast<uint32_t*>(g_vh + idx) = hi;
                    *reinterpret_cast<uint32_t*>(g_vl + idx) = lo;
                } else {
                    float sc = (s == 0) ? SCALE_ : 1.f;
                    float2 v = make_float2(vx * sc, vy * sc);
                    asm("cvt.rna.tf32.f32 %0, %1;"
                        : "=r"(*(uint32_t*)&v.x) : "f"(v.x));
                    asm("cvt.rna.tf32.f32 %0, %1;"
                        : "=r"(*(uint32_t*)&v.y) : "f"(v.y));
                    float* dst = (s == 0) ? g_q : g_k;
                    *reinterpret_cast<float2*>(dst + idx) = v;
                }
            }
        }
    }
}

/* ------------------------------------------------------------------ */
/* TF32 HMMA out-projection GEMM: tile 128x128, BK=32, 256 thr         */
/* (8 warps 4x2), 2 CTAs/SM, 3-stage mbarrier pipeline (R13 shape).    */
/* Grid 256 CTAs -> single resident wave. Bit-identical accumulation.  */
/* ------------------------------------------------------------------ */
#define G2ARR (128 * 128u)
#define G2STG (2 * G2ARR)
#define G2SMEM (128 + 3 * G2STG)

__global__ void __launch_bounds__(256, 2)
gemm_out(const float* __restrict__ A, const float* __restrict__ W,
         float* __restrict__ C, int K, int Nout)
{
    extern __shared__ float smem[];
    const uint32_t sb = smem_u32(smem);
    const uint32_t MBF = sb;
    const uint32_t MBE = sb + 24;
    const uint32_t DB  = sb + 128;

    const int tid  = threadIdx.x;
    const int lane = tid & 31;
    const int wid  = tid >> 5;
    const int wm   = wid & 3;
    const int wn   = wid >> 2;

    const int m0 = blockIdx.y * 128;
    const int j0 = blockIdx.x * 128;

    if (tid == 0) {
#pragma unroll
        for (int s = 0; s < 3; s++) {
            mbar_init(MBF + s * 8, 256);
            mbar_init(MBE + s * 8, 256);
        }
    }
    __syncthreads();

    const int q0 = tid & 7;

#define ISSUE_CHUNK2(kc, stage)                                               \
    do {                                                                      \
        const int koff = (kc) * 32;                                          \
        const uint32_t st_ = DB + (uint32_t)(stage) * G2STG;                 \
        _Pragma("unroll")                                                     \
        for (int i_ = 0; i_ < 4; i_++) {                                     \
            int r_ = (tid + i_ * 256) >> 3;                                  \
            uint32_t so_ = swzA((uint32_t)(r_ * 128 + q0 * 16));             \
            cp16(st_ + so_,         A + (size_t)(m0 + r_) * K + koff + q0 * 4); \
            cp16(st_ + G2ARR + so_, W + (size_t)(j0 + r_) * K + koff + q0 * 4); \
        }                                                                     \
        cp_arrive(MBF + (stage) * 8);                                        \
    } while (0)

    const int a_r8 = lane & 7;
    const int a_rh = (lane >> 3) & 1;
    const int a_ch = lane >> 4;
    const int b_rh = lane >> 4;
    const int b_ch = (lane >> 3) & 1;

    float acc[2][8][4];
#pragma unroll
    for (int i = 0; i < 2; i++)
#pragma unroll
        for (int j = 0; j < 8; j++)
#pragma unroll
            for (int c = 0; c < 4; c++) acc[i][j][c] = 0.f;

    const int nchunk = K >> 5;

    ISSUE_CHUNK2(0, 0);
    ISSUE_CHUNK2(1, 1);

    for (int kc = 0; kc < nchunk; kc++) {
        const int s = kc - (kc / 3) * 3;
        if (kc + 2 < nchunk) {
            const int s2 = (kc + 2) - ((kc + 2) / 3) * 3;
            if (kc >= 1) mbar_wait(MBE + s2 * 8, (uint32_t)(((kc - 1) / 3) & 1));
            ISSUE_CHUNK2(kc + 2, s2);
        }

        mbar_wait(MBF + s * 8, (uint32_t)((kc / 3) & 1));

        const uint32_t stg = DB + (uint32_t)s * G2STG;
        const uint32_t sA  = stg;
        const uint32_t sW  = stg + G2ARR;

#pragma unroll
        for (int ks = 0; ks < 4; ks++) {
            uint32_t a[2][4];
#pragma unroll
            for (int mt = 0; mt < 2; mt++) {
                int row   = wm * 32 + mt * 16 + a_r8 + a_rh * 8;
                int chunk = ks * 2 + a_ch;
                uint32_t addr = sA + swzA((uint32_t)(row * 128 + chunk * 16));
                ldsm4(addr, a[mt][0], a[mt][1], a[mt][2], a[mt][3]);
            }
#pragma unroll
            for (int np = 0; np < 4; np++) {
                int row   = wn * 64 + np * 16 + a_r8 + b_rh * 8;
                int chunk = ks * 2 + b_ch;
                uint32_t addr = sW + swzA((uint32_t)(row * 128 + chunk * 16));
                uint32_t bfr[4];
                ldsm4(addr, bfr[0], bfr[1], bfr[2], bfr[3]);
#pragma unroll
                for (int mt = 0; mt < 2; mt++) {
                    mma_tf32(acc[mt][np * 2 + 0], a[mt][0], a[mt][1], a[mt][2], a[mt][3],
                             bfr[0], bfr[1]);
                    mma_tf32(acc[mt][np * 2 + 1], a[mt][0], a[mt][1], a[mt][2], a[mt][3],
                             bfr[2], bfr[3]);
                }
            }
        }
        mbar_arrive(MBE + s * 8);
    }

    /* epilogue: plain fp32 store */
    const int grp = lane >> 2;
    const int qid = lane & 3;
#pragma unroll
    for (int mt = 0; mt < 2; mt++) {
#pragma unroll
        for (int nt = 0; nt < 8; nt++) {
            const float* c = acc[mt][nt];
            int row = m0 + wm * 32 + mt * 16 + grp;
            int col = j0 + wn * 64 + nt * 8 + qid * 2;
#pragma unroll
            for (int half = 0; half < 2; half++) {
                int m = row + half * 8;
                *reinterpret_cast<float2*>(C + (size_t)m * Nout + col) =
                    make_float2(c[half * 2], c[half * 2 + 1]);
            }
        }
    }
}

/* ------------------------------------------------------------------ */
/* Flash-attention (R16, unchanged): S tf32 single-pass, PV bf16 3-    */
/* split, 2-stage KV mbarrier pipeline, skip-warp fast path.           */
/* ------------------------------------------------------------------ */
#define ASTR 72
#define SMQ_B   128u
#define SMST0_B (SMQ_B + 32768u)
#define VH_OFF  16384u
#define VL_OFF  (16384u + 9216u)
#define STG_B   (16384u + 2u * 9216u)
#define ATT_SMEM_BYTES (SMST0_B + 2 * STG_B)

__global__ void __launch_bounds__(256, 2)
attn_mma()
{
    extern __shared__ char sraw[];
    const uint32_t sb0 = smem_u32(sraw);
    const uint32_t MBF = sb0;
    const uint32_t MBE = sb0 + 16;
    const uint32_t sQ  = sb0 + SMQ_B;

    const int qt = (N_ / 128 - 1) - (blockIdx.x >> 5);
    const int bh = blockIdx.x & 31;
    const int b  = bh >> 4;
    const int h  = bh & 15;

    const int tid  = threadIdx.x;
    const int lane = tid & 31;
    const int w    = tid >> 5;

    const float* Qb = g_q + (size_t)bh * N_ * DH_;
    const float* Kb = g_k + (size_t)bh * N_ * DH_;
    const __nv_bfloat16* Vbh = g_vh + (size_t)bh * N_ * DH_;
    const __nv_bfloat16* Vbl = g_vl + (size_t)bh * N_ * DH_;

    if (tid == 0) {
#pragma unroll
        for (int s = 0; s < 2; s++) {
            mbar_init(MBF + s * 8, 256);
            mbar_init(MBE + s * 8, 256);
        }
    }
    __syncthreads();

    const int kqr = tid >> 4;
    const int kqc = tid & 15;
    const int vr0 = tid >> 3;
    const int vc8 = (tid & 7) * 8;
    const uint32_t vso0 = (uint32_t)(vr0 * ASTR + vc8) * 2;
    const uint32_t vso1 = (uint32_t)((vr0 + 32) * ASTR + vc8) * 2;

#define ISSUE_KV(jt, stage)                                                   \
    do {                                                                      \
        const uint32_t st_ = sb0 + SMST0_B + (uint32_t)(stage) * STG_B;      \
        _Pragma("unroll")                                                     \
        for (int i_ = 0; i_ < 4; i_++) {                                     \
            int r_ = kqr + i_ * 16;                                          \
            uint32_t so_ = swzB((uint32_t)(r_ * 256 + kqc * 16));            \
            cp16(st_ + so_, Kb + (size_t)((jt) * 64 + r_) * DH_ + kqc * 4);  \
        }                                                                     \
        {                                                                     \
            const size_t g0 = (size_t)((jt) * 64 + vr0) * DH_ + vc8;         \
            const size_t g1 = (size_t)((jt) * 64 + vr0 + 32) * DH_ + vc8;    \
            cp16(st_ + VH_OFF + vso0, Vbh + g0);                             \
            cp16(st_ + VH_OFF + vso1, Vbh + g1);                             \
            cp16(st_ + VL_OFF + vso0, Vbl + g0);                             \
            cp16(st_ + VL_OFF + vso1, Vbl + g1);                             \
        }                                                                     \
        cp_arrive(MBF + (stage) * 8);                                        \
    } while (0)

    ISSUE_KV(0, 0);

#pragma unroll
    for (int it = 0; it < 8; it++) {
        int idx = tid + it * 256;
        int r   = idx >> 4;
        int c   = idx & 15;
        uint32_t so = swzB((uint32_t)(r * 256 + c * 16));
        *reinterpret_cast<uint4*>(sraw + SMQ_B + so) =
            *reinterpret_cast<const uint4*>(Qb + (size_t)(qt * 128 + r) * DH_ + c * 4);
    }
    __syncthreads();

    const int a_r8 = lane & 7;
    const int a_rh = (lane >> 3) & 1;
    const int a_ch = lane >> 4;
    const int b_rh = lane >> 4;
    const int b_ch = (lane >> 3) & 1;

    uint32_t qf[8][4];
    {
        const int qrow = w * 16 + a_r8 + a_rh * 8;
#pragma unroll
        for (int ks = 0; ks < 8; ks++) {
            int chunk = ks * 2 + a_ch;
            uint32_t addr = sQ + swzB((uint32_t)(qrow * 256 + chunk * 16));
            ldsm4(addr, qf[ks][0], qf[ks][1], qf[ks][2], qf[ks][3]);
        }
    }

    const uint32_t vpat = 2u * ((uint32_t)((lane & 15) * ASTR) + ((lane & 16) >> 1));

    float o[8][4];
#pragma unroll
    for (int i = 0; i < 8; i++)
#pragma unroll
        for (int c = 0; c < 4; c++) o[i][c] = 0.f;
    float mrow0 = -INFINITY, mrow1 = -INFINITY;
    float lrow0 = 0.f, lrow1 = 0.f;

    const int qglo   = qt * 128 + w * 16;
    const int ntiles = 2 * qt + 2;

    for (int jt = 0; jt < ntiles; jt++) {
        const int s = jt & 1;
        if (jt + 1 < ntiles) {
            const int s2 = (jt + 1) & 1;
            if (jt >= 1) mbar_wait(MBE + s2 * 8, (uint32_t)(((jt - 1) >> 1) & 1));
            ISSUE_KV(jt + 1, s2);
        }

        if (jt * 64 > qglo + 15) {
            mbar_arrive(MBE + s * 8);
            continue;
        }

        mbar_wait(MBF + s * 8, (uint32_t)((jt >> 1) & 1));

        {
            const uint32_t stg = sb0 + SMST0_B + (uint32_t)s * STG_B;
            const uint32_t sK  = stg;
            const uint32_t sVH = stg + VH_OFF;
            const uint32_t sVL = stg + VL_OFF;

            float sfr[8][4];
#pragma unroll
            for (int i = 0; i < 8; i++)
#pragma unroll
                for (int c = 0; c < 4; c++) sfr[i][c] = 0.f;

#pragma unroll
            for (int ks = 0; ks < 8; ks++) {
#pragma unroll
                for (int np = 0; np < 4; np++) {
                    int row   = np * 16 + a_r8 + b_rh * 8;
                    int chunk = ks * 2 + b_ch;
                    uint32_t addr = sK + swzB((uint32_t)(row * 256 + chunk * 16));
                    uint32_t bfr[4];
                    ldsm4(addr, bfr[0], bfr[1], bfr[2], bfr[3]);
                    mma_tf32(sfr[np * 2 + 0], qf[ks][0], qf[ks][1], qf[ks][2], qf[ks][3],
                             bfr[0], bfr[1]);
                    mma_tf32(sfr[np * 2 + 1], qf[ks][0], qf[ks][1], qf[ks][2], qf[ks][3],
                             bfr[2], bfr[3]);
                }
            }

            const int r0 = qglo + (lane >> 2);
            const int r1 = r0 + 8;
            if (jt * 64 + 63 > qglo) {
                const int colb = jt * 64 + (lane & 3) * 2;
#pragma unroll
                for (int nt = 0; nt < 8; nt++) {
                    int c0 = colb + nt * 8;
                    if (c0 > r0)     sfr[nt][0] = -INFINITY;
                    if (c0 + 1 > r0) sfr[nt][1] = -INFINITY;
                    if (c0 > r1)     sfr[nt][2] = -INFINITY;
                    if (c0 + 1 > r1) sfr[nt][3] = -INFINITY;
                }
            }

            float mt0 = sfr[0][0], mt1 = sfr[0][2];
#pragma unroll
            for (int nt = 0; nt < 8; nt++) {
                mt0 = fmaxf(mt0, fmaxf(sfr[nt][0], sfr[nt][1]));
                mt1 = fmaxf(mt1, fmaxf(sfr[nt][2], sfr[nt][3]));
            }
            mt0 = fmaxf(mt0, __shfl_xor_sync(0xffffffffu, mt0, 1));
            mt0 = fmaxf(mt0, __shfl_xor_sync(0xffffffffu, mt0, 2));
            mt1 = fmaxf(mt1, __shfl_xor_sync(0xffffffffu, mt1, 1));
            mt1 = fmaxf(mt1, __shfl_xor_sync(0xffffffffu, mt1, 2));

            const float mn0 = fmaxf(mrow0, mt0);
            const float mn1 = fmaxf(mrow1, mt1);
            const float al0 = __expf(mrow0 - mn0);
            const float al1 = __expf(mrow1 - mn1);

            float ps0 = 0.f, ps1 = 0.f;
#pragma unroll
            for (int nt = 0; nt < 8; nt++) {
                sfr[nt][0] = __expf(sfr[nt][0] - mn0);
                sfr[nt][1] = __expf(sfr[nt][1] - mn0);
                sfr[nt][2] = __expf(sfr[nt][2] - mn1);
                sfr[nt][3] = __expf(sfr[nt][3] - mn1);
                ps0 += sfr[nt][0] + sfr[nt][1];
                ps1 += sfr[nt][2] + sfr[nt][3];
            }
            ps0 += __shfl_xor_sync(0xffffffffu, ps0, 1);
            ps0 += __shfl_xor_sync(0xffffffffu, ps0, 2);
            ps1 += __shfl_xor_sync(0xffffffffu, ps1, 1);
            ps1 += __shfl_xor_sync(0xffffffffu, ps1, 2);

            lrow0 = lrow0 * al0 + ps0;
            lrow1 = lrow1 * al1 + ps1;
#pragma unroll
            for (int nt = 0; nt < 8; nt++) {
                o[nt][0] *= al0; o[nt][1] *= al0;
                o[nt][2] *= al1; o[nt][3] *= al1;
            }
            mrow0 = mn0;
            mrow1 = mn1;

#pragma unroll
            for (int ks = 0; ks < 4; ks++) {
                uint32_t ph[4], pl[4];
                split2(sfr[2 * ks][0],     sfr[2 * ks][1],     ph[0], pl[0]);
                split2(sfr[2 * ks][2],     sfr[2 * ks][3],     ph[1], pl[1]);
                split2(sfr[2 * ks + 1][0], sfr[2 * ks + 1][1], ph[2], pl[2]);
                split2(sfr[2 * ks + 1][2], sfr[2 * ks + 1][3], ph[3], pl[3]);
#pragma unroll
                for (int np = 0; np < 4; np++) {
                    const uint32_t voff = vpat + 2u * (ks * 16 * ASTR + np * 16);
                    uint32_t bh4[4], bl4[4];
                    ldsm4t(sVH + voff, bh4[0], bh4[1], bh4[2], bh4[3]);
                    ldsm4t(sVL + voff, bl4[0], bl4[1], bl4[2], bl4[3]);
#pragma unroll
                    for (int sub = 0; sub < 2; sub++) {
                        float* c = o[np * 2 + sub];
                        mma16816(c, ph[0], ph[1], ph[2], ph[3],
                                 bh4[sub * 2], bh4[sub * 2 + 1]);
                        mma16816(c, ph[0], ph[1], ph[2], ph[3],
                                 bl4[sub * 2], bl4[sub * 2 + 1]);
                        mma16816(c, pl[0], pl[1], pl[2], pl[3],
                                 bh4[sub * 2], bh4[sub * 2 + 1]);
                    }
                }
            }
        }

        mbar_arrive(MBE + s * 8);
    }

    /* ---- epilogue: normalize, write tf32-rounded ao ---- */
    const float i0 = 1.f / lrow0;
    const float i1 = 1.f / lrow1;
    const int r0 = qt * 128 + w * 16 + (lane >> 2);
    const size_t base0 = ((size_t)b * N_ + r0) * D_ + h * DH_ + (lane & 3) * 2;
    const size_t base1 = base0 + 8 * D_;
#pragma unroll
    for (int nt = 0; nt < 8; nt++) {
        float2 v0 = make_float2(o[nt][0] * i0, o[nt][1] * i0);
        float2 v1 = make_float2(o[nt][2] * i1, o[nt][3] * i1);
        asm("cvt.rna.tf32.f32 %0, %1;" : "=r"(*(uint32_t*)&v0.x) : "f"(v0.x));
        asm("cvt.rna.tf32.f32 %0, %1;" : "=r"(*(uint32_t*)&v0.y) : "f"(v0.y));
        asm("cvt.rna.tf32.f32 %0, %1;" : "=r"(*(uint32_t*)&v1.x) : "f"(v1.x));
        asm("cvt.rna.tf32.f32 %0, %1;" : "=r"(*(uint32_t*)&v1.y) : "f"(v1.y));
        *reinterpret_cast<float2*>(g_aor + base0 + nt * 8) = v0;
        *reinterpret_cast<float2*>(g_aor + base1 + nt * 8) = v1;
    }
}

/* ------------------------------------------------------------------ */
extern "C" void kernel_launch(void* const* d_in, const int* in_sizes, int n_in,
                              void* d_out, int out_size)
{
    const float* x    = (const float*)d_in[0];
    /* d_in[1] = mask (static causal structure, unused) */
    const float* Wqkv = (const float*)d_in[2];
    const float* Wout = (const float*)d_in[3];
    float* out = (float*)d_out;

    float *xr, *wqr, *wor, *aor;
    cudaGetSymbolAddress((void**)&xr,  g_xr);
    cudaGetSymbolAddress((void**)&wqr, g_wqr);
    cudaGetSymbolAddress((void**)&wor, g_wor);
    cudaGetSymbolAddress((void**)&aor, g_aor);

    /* 0. fused pre-rounding of all inputs to tf32 */
    round_all<<<2048, 256>>>(x, Wqkv, Wout);

    cudaFuncSetAttribute(gemm_qkv,
                         cudaFuncAttributeMaxDynamicSharedMemorySize, GEMM_SMEM);
    cudaFuncSetAttribute(gemm_out,
                         cudaFuncAttributeMaxDynamicSharedMemorySize, G2SMEM);

    /* 1. QKV projection (tf32) -> q/k tf32 fp32 (q scaled), v bf16 hi/lo */
    gemm_qkv<<<dim3(3072 / 128, 4096 / 256), 512, GEMM_SMEM>>>(xr, wqr, D_);

    /* 2. causal flash attention (S: tf32; PV: bf16 split) -> tf32 ao */
    cudaFuncSetAttribute(attn_mma,
                         cudaFuncAttributeMaxDynamicSharedMemorySize, ATT_SMEM_BYTES);
    attn_mma<<<dim3((N_ / 128) * 32), 256, ATT_SMEM_BYTES>>>();

    /* 3. output projection (tf32, 128x128 tile, 2 CTA/SM, 1 wave) */
    gemm_out<<<dim3(1024 / 128, 4096 / 128), 256, G2SMEM>>>(
        aor, wor, out, D_, D_);
}